// round 4
// baseline (speedup 1.0000x reference)
#include <cuda_runtime.h>
#include <math.h>

#define HH 2048
#define WW 2048
#define HWFULL (HH * WW)
#define NE 1024              // E maps / pyr1 are 1024x1024

// ---------------- static scratch (no allocations allowed) ----------------
__device__ __align__(16) float g_pyr1[3 * 1024 * 1024];
__device__ __align__(16) float g_pyr2[3 * 512 * 512];
__device__ __align__(16) float g_pyr3[3 * 256 * 256];
__device__ __align__(16) float g_pyr4[3 * 128 * 128];
__device__ __align__(16) float g_pyr5[3 * 64 * 64];
__device__ __align__(16) float g_E2[3 * 1024 * 1024];
__device__ __align__(16) float g_E3[3 * 1024 * 1024];
__device__ __align__(16) float g_E4[3 * 1024 * 1024];
__device__ __align__(16) float g_E5[3 * 1024 * 1024];

// ---------------- K1: fused blur (3-tap) + 2x2 mean, img -> pyr1 ----------
__global__ void blur_down_kernel(const float* __restrict__ in, float* __restrict__ out,
                                 int no, float De, float Dm) {
    int x = blockIdx.x * blockDim.x + threadIdx.x;
    int y = blockIdx.y * blockDim.y + threadIdx.y;
    int c = blockIdx.z;
    if (x >= no || y >= no) return;
    int ni = 2 * no;
    const float2* ip = (const float2*)(in) + (size_t)c * ni * no;
    float acc = 0.f;
#pragma unroll
    for (int j = 0; j < 4; j++) {
        int r = 2 * y - 1 + j;
        if (r < 0 || r >= ni) continue;
        const float2* row = ip + (size_t)r * no;
        float2 Bc = row[x];
        float a = (x > 0) ? row[x - 1].y : 0.f;
        float d = (x < no - 1) ? row[x + 1].x : 0.f;
        float wj = (j == 0 || j == 3) ? De : Dm;
        acc += wj * (De * a + Dm * Bc.x + Dm * Bc.y + De * d);
    }
    out[(size_t)c * no * no + (size_t)y * no + x] = acc;
}

// ---------------- K2: fused down chain pyr1 -> pyr2..pyr5 -----------------
// Block owns pyr5 8x8 tile; chains in smem from a 158x158 pyr1 window.
// Zero-pad semantics: halo zero-fill + zeroing out-of-global-range outputs.
__device__ __forceinline__ void dstage(const float* __restrict__ sin, int pin,
                                       float* __restrict__ sout, int so,
                                       int offR, int offC, int n,
                                       float De, float Dm, int tid) {
    for (int i = tid; i < so * so; i += 256) {
        int v = i / so, u = i - v * so;
        int gy = offR + v, gx = offC + u;
        float val = 0.f;
        if (gy >= 0 && gy < n && gx >= 0 && gx < n) {
            float acc = 0.f;
#pragma unroll
            for (int j = 0; j < 4; j++) {
                const float* row = sin + (2 * v + j) * pin + 2 * u;
                float wj = (j == 0 || j == 3) ? De : Dm;
                acc += wj * (De * row[0] + Dm * row[1] + Dm * row[2] + De * row[3]);
            }
            val = acc;
        }
        sout[i] = val;
    }
}

__global__ __launch_bounds__(256)
void down_chain_kernel(const float* __restrict__ pyr1,
                       float* __restrict__ pyr2, float* __restrict__ pyr3,
                       float* __restrict__ pyr4, float* __restrict__ pyr5,
                       float De, float Dm) {
    extern __shared__ float sm[];
    float* s1 = sm;                       // 158*158 = 24964
    float* s2 = s1 + 24964;               // 78*78  = 6084
    float* s3 = s2 + 6084;                // 38*38  = 1444
    float* s4 = s3 + 1444;                // 18*18  = 324
    int bx = blockIdx.x, by = blockIdx.y, c = blockIdx.z;
    int tid = threadIdx.x;

    const float* p1 = pyr1 + (size_t)c * 1024 * 1024;
    int r0 = 128 * by - 15, c0 = 128 * bx - 15;
    for (int i = tid; i < 158 * 158; i += 256) {
        int v = i / 158, u = i - v * 158;
        int gr = r0 + v, gc = c0 + u;
        float val = 0.f;
        if (gr >= 0 && gr < 1024 && gc >= 0 && gc < 1024)
            val = p1[(size_t)gr * 1024 + gc];
        s1[i] = val;
    }
    __syncthreads();

    dstage(s1, 158, s2, 78, 64 * by - 7, 64 * bx - 7, 512, De, Dm, tid);
    __syncthreads();
    dstage(s2, 78, s3, 38, 32 * by - 3, 32 * bx - 3, 256, De, Dm, tid);
    __syncthreads();
    dstage(s3, 38, s4, 18, 16 * by - 1, 16 * bx - 1, 128, De, Dm, tid);
    __syncthreads();

    // owned writes
    float* p2 = pyr2 + (size_t)c * 512 * 512;
    for (int i = tid; i < 64 * 64; i += 256) {
        int v = i >> 6, u = i & 63;
        p2[(size_t)(64 * by + v) * 512 + 64 * bx + u] = s2[(v + 7) * 78 + u + 7];
    }
    float* p3 = pyr3 + (size_t)c * 256 * 256;
    for (int i = tid; i < 32 * 32; i += 256) {
        int v = i >> 5, u = i & 31;
        p3[(size_t)(32 * by + v) * 256 + 32 * bx + u] = s3[(v + 3) * 38 + u + 3];
    }
    float* p4 = pyr4 + (size_t)c * 128 * 128;
    for (int i = tid; i < 16 * 16; i += 256) {
        int v = i >> 4, u = i & 15;
        p4[(size_t)(16 * by + v) * 128 + 16 * bx + u] = s4[(v + 1) * 18 + u + 1];
    }
    float* p5 = pyr5 + (size_t)c * 64 * 64;
    for (int i = tid; i < 8 * 8; i += 256) {
        int v = i >> 3, u = i & 7;
        float acc = 0.f;
#pragma unroll
        for (int j = 0; j < 4; j++) {
            const float* row = s4 + (2 * v + j) * 18 + 2 * u;
            float wj = (j == 0 || j == 3) ? De : Dm;
            acc += wj * (De * row[0] + Dm * row[1] + Dm * row[2] + De * row[3]);
        }
        p5[(size_t)(8 * by + v) * 64 + 8 * bx + u] = acc;
    }
}

// ---------------- composite (bilinear x2 upsample -> 3-tap blur) weights ---
__device__ __forceinline__ void ub_weights(int o, int n, float w0, float w1,
                                           int& base, float w[3]) {
    base = (o >> 1) - 1;
    w[0] = w[1] = w[2] = 0.f;
    int n2 = n * 2;
#pragma unroll
    for (int d = -1; d <= 1; ++d) {
        int p = o + d;
        if (p < 0 || p >= n2) continue;
        float bw = (d == 0) ? w0 : w1;
        int i = p >> 1;
        if ((p & 1) == 0) {
            w[i - 1 - base] += 0.25f * bw;
            w[i - base]     += 0.75f * bw;
        } else {
            w[i - base]     += 0.75f * bw;
            w[i + 1 - base] += 0.25f * bw;
        }
    }
}

// per-pixel up+blur on a global image (used by blend slow path)
__device__ float up_pixel(const float* __restrict__ E, int n, int ox, int oy,
                          float w0, float w1) {
    int by, bx;
    float wy[3], wx[3];
    ub_weights(oy, n, w0, w1, by, wy);
    ub_weights(ox, n, w0, w1, bx, wx);
    int ry[3], rx[3];
#pragma unroll
    for (int j = 0; j < 3; j++) {
        ry[j] = min(max(by + j, 0), n - 1);
        rx[j] = min(max(bx + j, 0), n - 1);
    }
    float s = 0.f;
#pragma unroll
    for (int jy = 0; jy < 3; jy++) {
        const float* row = E + (size_t)ry[jy] * n;
        s += wy[jy] * (wx[0] * row[rx[0]] + wx[1] * row[rx[1]] + wx[2] * row[rx[2]]);
    }
    return s;
}

// ---------------- K3: fused expansion chains pyrL -> E_L -------------------
// Block computes a 64x64 tile of E_L by chaining up+blur steps in smem.
__global__ __launch_bounds__(256)
void expand_kernel(const float* __restrict__ pyr2, const float* __restrict__ pyr3,
                   const float* __restrict__ pyr4, const float* __restrict__ pyr5,
                   float* __restrict__ E2, float* __restrict__ E3,
                   float* __restrict__ E4, float* __restrict__ E5,
                   float w0, float w1) {
    __shared__ float bufA[34 * 34];
    __shared__ float bufB[34 * 34];
    int z = blockIdx.z;
    int c = z >> 2;
    int Lm2 = z & 3;
    int depth = Lm2 + 1;                 // number of up steps
    int nL = 1024 >> depth;              // pyr level size: 512,256,128,64

    const float* pin = pyr2;
    float* pout = E2;
    if (Lm2 == 1) { pin = pyr3; pout = E3; }
    else if (Lm2 == 2) { pin = pyr4; pout = E4; }
    else if (Lm2 == 3) { pin = pyr5; pout = E5; }
    pin += (size_t)c * nL * nL;
    pout += (size_t)c * NE * NE;

    int offR[5], szR[5], offC[5], szC[5];
    offR[depth] = 64 * blockIdx.y; szR[depth] = 64;
    offC[depth] = 64 * blockIdx.x; szC[depth] = 64;
    for (int d = depth; d >= 1; --d) {
        int nIn = nL << (d - 1);
        int a = offR[d], b = a + szR[d] - 1;
        int aI = max(0, (a >> 1) - 1), bI = min(nIn - 1, (b >> 1) + 1);
        offR[d - 1] = aI; szR[d - 1] = bI - aI + 1;
        a = offC[d]; b = a + szC[d] - 1;
        aI = max(0, (a >> 1) - 1); bI = min(nIn - 1, (b >> 1) + 1);
        offC[d - 1] = aI; szC[d - 1] = bI - aI + 1;
    }

    int tid = threadIdx.x;
    // load stage-0 window from pyr level (always fully in range)
    for (int i = tid; i < szR[0] * szC[0]; i += 256) {
        int v = i / szC[0], u = i - v * szC[0];
        bufA[i] = pin[(size_t)(offR[0] + v) * nL + offC[0] + u];
    }
    __syncthreads();

    float* cur = bufA;
    float* nxt = bufB;
    for (int d = 1; d <= depth; ++d) {
        int nIn = nL << (d - 1);
        int pitch = szC[d - 1];
        int soR = szR[d], soC = szC[d];
        for (int i = tid; i < soR * soC; i += 256) {
            int v = i / soC, u = i - v * soC;
            int oy = offR[d] + v, ox = offC[d] + u;
            int byq, bxq;
            float wy[3], wxq[3];
            ub_weights(oy, nIn, w0, w1, byq, wy);
            ub_weights(ox, nIn, w0, w1, bxq, wxq);
            int ry[3], rx[3];
#pragma unroll
            for (int j = 0; j < 3; j++) {
                ry[j] = min(max(byq + j, 0), nIn - 1) - offR[d - 1];
                rx[j] = min(max(bxq + j, 0), nIn - 1) - offC[d - 1];
            }
            float s = 0.f;
#pragma unroll
            for (int jy = 0; jy < 3; jy++) {
                const float* row = cur + ry[jy] * pitch;
                s += wy[jy] * (wxq[0] * row[rx[0]] + wxq[1] * row[rx[1]] +
                               wxq[2] * row[rx[2]]);
            }
            if (d == depth) pout[(size_t)oy * NE + ox] = s;
            else nxt[v * soC + u] = s;
        }
        __syncthreads();
        float* t = cur; cur = nxt; nxt = t;
    }
}

// ---------------- blend helpers --------------------------------------------
__device__ __forceinline__ const float* level_ptr(int l, const float* E1, const float* E2,
                                                  const float* E3, const float* E4,
                                                  const float* E5) {
    const float* p = E1;
    p = (l == 2) ? E2 : p;
    p = (l == 3) ? E3 : p;
    p = (l == 4) ? E4 : p;
    p = (l == 5) ? E5 : p;
    return p;
}

__device__ __forceinline__ float blend_B(int l, float R) {
    float sprev = exp2f((float)(l - 3));
    float ap = sprev * R * (1.0f / 0.248f);
    float tp = expf(-(ap * ap) * 3.0f);
    float tc = 0.f;
    if (l < 5) {
        float ac = 2.0f * ap;
        tc = expf(-(ac * ac) * 3.0f);
    }
    return (0.5f - tc) / (tp - tc + 1e-5f);
}

__device__ void pixel_slow(int x, int y, int l, float R,
                           const float* __restrict__ img,
                           const float* __restrict__ E1, const float* __restrict__ E2,
                           const float* __restrict__ E3, const float* __restrict__ E4,
                           const float* __restrict__ E5, float* __restrict__ out,
                           float w0, float w1) {
    int pix = y * WW + x;
    if (l == 0) {
        out[pix] = img[pix];
        out[pix + HWFULL] = img[pix + HWFULL];
        out[pix + 2 * HWFULL] = img[pix + 2 * HWFULL];
        return;
    }
    float B = blend_B(l, R);
    const float* Ecur = level_ptr(l, E1, E2, E3, E4, E5);
    const float* Eprev = level_ptr(l - 1, E1, E2, E3, E4, E5);
#pragma unroll
    for (int c = 0; c < 3; c++) {
        float vc = up_pixel(Ecur + c * NE * NE, NE, x, y, w0, w1);
        float vp = (l == 1) ? img[pix + c * HWFULL]
                            : up_pixel(Eprev + c * NE * NE, NE, x, y, w0, w1);
        out[pix + c * HWFULL] = B * vp + (1.f - B) * vc;
    }
}

__device__ void quad_global(int qx, int qy, int l0, const float B[2][2],
                            const float* __restrict__ img,
                            const float* __restrict__ cur, const float* __restrict__ prv,
                            float* __restrict__ out,
                            float we0, float we1, float we2) {
    int pix0 = (2 * qy) * WW + 2 * qx;
    int wbase = (qy - 1) * NE + (qx - 1);
#pragma unroll
    for (int c = 0; c < 3; c++) {
        const float* pc = cur + c * NE * NE + wbase;
        float he[3], ho[3];
#pragma unroll
        for (int j = 0; j < 3; j++) {
            float a = pc[j * NE], b = pc[j * NE + 1], d = pc[j * NE + 2];
            he[j] = we0 * a + we1 * b + we2 * d;
            ho[j] = we2 * a + we1 * b + we0 * d;
        }
        float vc[2][2];
        vc[0][0] = we0 * he[0] + we1 * he[1] + we2 * he[2];
        vc[0][1] = we0 * ho[0] + we1 * ho[1] + we2 * ho[2];
        vc[1][0] = we2 * he[0] + we1 * he[1] + we0 * he[2];
        vc[1][1] = we2 * ho[0] + we1 * ho[1] + we0 * ho[2];

        float vp[2][2];
        if (l0 == 1) {
            float2 i0 = *(const float2*)(img + pix0 + c * HWFULL);
            float2 i1 = *(const float2*)(img + pix0 + WW + c * HWFULL);
            vp[0][0] = i0.x; vp[0][1] = i0.y; vp[1][0] = i1.x; vp[1][1] = i1.y;
        } else {
            const float* pp = prv + c * NE * NE + wbase;
            float pe[3], po[3];
#pragma unroll
            for (int j = 0; j < 3; j++) {
                float a = pp[j * NE], b = pp[j * NE + 1], d = pp[j * NE + 2];
                pe[j] = we0 * a + we1 * b + we2 * d;
                po[j] = we2 * a + we1 * b + we0 * d;
            }
            vp[0][0] = we0 * pe[0] + we1 * pe[1] + we2 * pe[2];
            vp[0][1] = we0 * po[0] + we1 * po[1] + we2 * po[2];
            vp[1][0] = we2 * pe[0] + we1 * pe[1] + we0 * pe[2];
            vp[1][1] = we2 * po[0] + we1 * po[1] + we0 * po[2];
        }
        float2 o0, o1;
        o0.x = B[0][0] * vp[0][0] + (1.f - B[0][0]) * vc[0][0];
        o0.y = B[0][1] * vp[0][1] + (1.f - B[0][1]) * vc[0][1];
        o1.x = B[1][0] * vp[1][0] + (1.f - B[1][0]) * vc[1][0];
        o1.y = B[1][1] * vp[1][1] + (1.f - B[1][1]) * vc[1][1];
        *(float2*)(out + pix0 + c * HWFULL) = o0;
        *(float2*)(out + pix0 + WW + c * HWFULL) = o1;
    }
}

// ---------------- K4: blend with block-uniform smem fast path --------------
#define TQX 32
#define TQY 8
#define TPITCH 34
#define TROWS 10

__global__ __launch_bounds__(256)
void blend_quad_kernel(const float* __restrict__ img, const float* __restrict__ fixs,
                       const float* __restrict__ E1, const float* __restrict__ E2,
                       const float* __restrict__ E3, const float* __restrict__ E4,
                       const float* __restrict__ E5, float* __restrict__ out,
                       float w0, float w1, float we0, float we1, float we2,
                       float om0, float om1, float om2, float om3, float om4) {
    __shared__ float s_cur[3][TROWS][TPITCH];
    __shared__ float s_prv[3][TROWS][TPITCH];
    __shared__ int s_ref;

    int tx = threadIdx.x, ty = threadIdx.y;
    int qx = blockIdx.x * TQX + tx;
    int qy = blockIdx.y * TQY + ty;

    float fx[4], fy[4];
#pragma unroll
    for (int k = 0; k < 4; k++) { fx[k] = fixs[2 * k]; fy[k] = fixs[2 * k + 1]; }

    float omega[6] = {om0, om1, om2, om3, om4, 0.f};
    int lv[2][2];
    float Rv[2][2];
#pragma unroll
    for (int py = 0; py < 2; py++)
#pragma unroll
        for (int px = 0; px < 2; px++) {
            float xf = (float)(2 * qx + px), yf = (float)(2 * qy + py);
            float d2 = 3.4e38f;
#pragma unroll
            for (int k = 0; k < 4; k++) {
                float dx = xf - fx[k], dy = yf - fy[k];
                d2 = fminf(d2, dx * dx + dy * dy);
            }
            float theta = sqrtf(d2) * (1.0f / 7.5f);
            float R = 2.5f / (theta + 2.5f);
            Rv[py][px] = R;
            int l = 0;
#pragma unroll
            for (int i = 1; i <= 5; i++)
                if (R >= omega[i] && R <= omega[i - 1]) l = i;
            lv[py][px] = l;
        }

    if (tx == 0 && ty == 0) s_ref = lv[0][0];
    __syncthreads();
    int lref = s_ref;
    bool mine_uniform = (lv[0][0] == lref) && (lv[0][1] == lref) &&
                        (lv[1][0] == lref) && (lv[1][1] == lref);
    int all_uni = __syncthreads_and(mine_uniform ? 1 : 0);
    bool block_border = (blockIdx.x == 0) || (blockIdx.x == gridDim.x - 1) ||
                        (blockIdx.y == 0) || (blockIdx.y == gridDim.y - 1);

    int pix0 = (2 * qy) * WW + 2 * qx;

    if (all_uni && !block_border) {
        if (lref == 0) {
#pragma unroll
            for (int c = 0; c < 3; c++) {
                *(float2*)(out + pix0 + c * HWFULL) =
                    *(const float2*)(img + pix0 + c * HWFULL);
                *(float2*)(out + pix0 + WW + c * HWFULL) =
                    *(const float2*)(img + pix0 + WW + c * HWFULL);
            }
            return;
        }
        const float* cur = level_ptr(lref, E1, E2, E3, E4, E5);
        const float* prv = level_ptr(lref - 1, E1, E2, E3, E4, E5);
        int ox0 = blockIdx.x * TQX - 1;
        int oy0 = blockIdx.y * TQY - 1;
        int tid = ty * TQX + tx;
        int nfill = 3 * TROWS * TPITCH;
        for (int i = tid; i < nfill; i += 256) {
            int c = i / (TROWS * TPITCH);
            int rem = i - c * (TROWS * TPITCH);
            int r = rem / TPITCH, col = rem - r * TPITCH;
            size_t g = (size_t)c * NE * NE + (size_t)(oy0 + r) * NE + (ox0 + col);
            s_cur[c][r][col] = cur[g];
            if (lref >= 2) s_prv[c][r][col] = prv[g];
        }
        __syncthreads();

        float B[2][2];
#pragma unroll
        for (int py = 0; py < 2; py++)
#pragma unroll
            for (int px = 0; px < 2; px++)
                B[py][px] = blend_B(lref, Rv[py][px]);

#pragma unroll
        for (int c = 0; c < 3; c++) {
            float he[3], ho[3];
#pragma unroll
            for (int j = 0; j < 3; j++) {
                float a = s_cur[c][ty + j][tx];
                float b = s_cur[c][ty + j][tx + 1];
                float d = s_cur[c][ty + j][tx + 2];
                he[j] = we0 * a + we1 * b + we2 * d;
                ho[j] = we2 * a + we1 * b + we0 * d;
            }
            float vc[2][2];
            vc[0][0] = we0 * he[0] + we1 * he[1] + we2 * he[2];
            vc[0][1] = we0 * ho[0] + we1 * ho[1] + we2 * ho[2];
            vc[1][0] = we2 * he[0] + we1 * he[1] + we0 * he[2];
            vc[1][1] = we2 * ho[0] + we1 * ho[1] + we0 * ho[2];

            float vp[2][2];
            if (lref == 1) {
                float2 i0 = *(const float2*)(img + pix0 + c * HWFULL);
                float2 i1 = *(const float2*)(img + pix0 + WW + c * HWFULL);
                vp[0][0] = i0.x; vp[0][1] = i0.y; vp[1][0] = i1.x; vp[1][1] = i1.y;
            } else {
                float pe[3], po[3];
#pragma unroll
                for (int j = 0; j < 3; j++) {
                    float a = s_prv[c][ty + j][tx];
                    float b = s_prv[c][ty + j][tx + 1];
                    float d = s_prv[c][ty + j][tx + 2];
                    pe[j] = we0 * a + we1 * b + we2 * d;
                    po[j] = we2 * a + we1 * b + we0 * d;
                }
                vp[0][0] = we0 * pe[0] + we1 * pe[1] + we2 * pe[2];
                vp[0][1] = we0 * po[0] + we1 * po[1] + we2 * po[2];
                vp[1][0] = we2 * pe[0] + we1 * pe[1] + we0 * pe[2];
                vp[1][1] = we2 * po[0] + we1 * po[1] + we0 * po[2];
            }
            float2 o0, o1;
            o0.x = B[0][0] * vp[0][0] + (1.f - B[0][0]) * vc[0][0];
            o0.y = B[0][1] * vp[0][1] + (1.f - B[0][1]) * vc[0][1];
            o1.x = B[1][0] * vp[1][0] + (1.f - B[1][0]) * vc[1][0];
            o1.y = B[1][1] * vp[1][1] + (1.f - B[1][1]) * vc[1][1];
            *(float2*)(out + pix0 + c * HWFULL) = o0;
            *(float2*)(out + pix0 + WW + c * HWFULL) = o1;
        }
        return;
    }

    // fallback paths
    int l0 = lv[0][0];
    bool uni = (lv[0][1] == l0) && (lv[1][0] == l0) && (lv[1][1] == l0);
    bool qborder = (qx == 0) | (qx >= NE - 1) | (qy == 0) | (qy >= NE - 1);

    if (uni && l0 == 0) {
#pragma unroll
        for (int c = 0; c < 3; c++) {
            *(float2*)(out + pix0 + c * HWFULL) =
                *(const float2*)(img + pix0 + c * HWFULL);
            *(float2*)(out + pix0 + WW + c * HWFULL) =
                *(const float2*)(img + pix0 + WW + c * HWFULL);
        }
        return;
    }
    if (!uni || qborder) {
#pragma unroll
        for (int py = 0; py < 2; py++)
#pragma unroll
            for (int px = 0; px < 2; px++)
                pixel_slow(2 * qx + px, 2 * qy + py, lv[py][px], Rv[py][px],
                           img, E1, E2, E3, E4, E5, out, w0, w1);
        return;
    }
    float B[2][2];
#pragma unroll
    for (int py = 0; py < 2; py++)
#pragma unroll
        for (int px = 0; px < 2; px++)
            B[py][px] = blend_B(l0, Rv[py][px]);
    const float* cur = level_ptr(l0, E1, E2, E3, E4, E5);
    const float* prv = level_ptr(l0 - 1, E1, E2, E3, E4, E5);
    quad_global(qx, qy, l0, B, img, cur, prv, out, we0, we1, we2);
}

// ---------------- host launch ---------------------------------------------
extern "C" void kernel_launch(void* const* d_in, const int* in_sizes, int n_in,
                              void* d_out, int out_size) {
    const float* img = (const float*)d_in[0];
    const float* fixs = (const float*)d_in[1];
    float* out = (float*)d_out;

    float *pyr1, *pyr2, *pyr3, *pyr4, *pyr5, *E2, *E3, *E4, *E5;
    cudaGetSymbolAddress((void**)&pyr1, g_pyr1);
    cudaGetSymbolAddress((void**)&pyr2, g_pyr2);
    cudaGetSymbolAddress((void**)&pyr3, g_pyr3);
    cudaGetSymbolAddress((void**)&pyr4, g_pyr4);
    cudaGetSymbolAddress((void**)&pyr5, g_pyr5);
    cudaGetSymbolAddress((void**)&E2, g_E2);
    cudaGetSymbolAddress((void**)&E3, g_E3);
    cudaGetSymbolAddress((void**)&E4, g_E4);
    cudaGetSymbolAddress((void**)&E5, g_E5);

    // Gaussian taps (w2 ~ 7.5e-15 dropped from taps; kept in normalization)
    double s2 = 2.0 * 0.248 * 0.248;
    double g1 = exp(-1.0 / s2);
    double g2 = exp(-4.0 / s2);
    double nrm = 1.0 + 2.0 * g1 + 2.0 * g2;
    float w0 = (float)(1.0 / nrm);
    float w1 = (float)(g1 / nrm);
    float De = (float)(0.5 * g1 / nrm);
    float Dm = (float)(0.5 * (1.0 + g1) / nrm);
    float we0 = 0.25f * w0 + 0.75f * w1;
    float we1 = 0.75f * w0 + w1;
    float we2 = 0.25f * w1;

    double ob = sqrt(log(2.0) / 3.0) * 0.248;
    float om0 = (float)(ob * 4.0);
    float om1 = (float)(ob * 2.0);
    float om2 = (float)(ob);
    float om3 = (float)(ob * 0.5);
    float om4 = (float)(ob * 0.25);

    // K2 needs 131264 B of dynamic smem
    const int K2_SMEM = (24964 + 6084 + 1444 + 324) * 4;
    cudaFuncSetAttribute(down_chain_kernel,
                         cudaFuncAttributeMaxDynamicSharedMemorySize, K2_SMEM);

    dim3 blk(32, 8);

    // K1: img -> pyr1
    blur_down_kernel<<<dim3(32, 128, 3), blk>>>(img, pyr1, 1024, De, Dm);

    // K2: pyr1 -> pyr2..pyr5 (one launch)
    down_chain_kernel<<<dim3(8, 8, 3), 256, K2_SMEM>>>(pyr1, pyr2, pyr3, pyr4, pyr5,
                                                       De, Dm);

    // K3: pyr2..pyr5 -> E2..E5 (one launch)
    expand_kernel<<<dim3(16, 16, 12), 256>>>(pyr2, pyr3, pyr4, pyr5,
                                             E2, E3, E4, E5, w0, w1);

    // K4: blend
    blend_quad_kernel<<<dim3(NE / 32, NE / 8), blk>>>(img, fixs, pyr1, E2, E3, E4, E5,
                                                      out, w0, w1, we0, we1, we2,
                                                      om0, om1, om2, om3, om4);
}

// round 5
// speedup vs baseline: 1.6003x; 1.6003x over previous
#include <cuda_runtime.h>
#include <math.h>

#define HH 2048
#define WW 2048
#define HWFULL (HH * WW)
#define NE 1024              // E maps (half-res expansions) are 1024x1024

// ---------------- static scratch (no allocations allowed) ----------------
__device__ __align__(16) float g_pyr1[3 * 1024 * 1024];
__device__ __align__(16) float g_pyr2[3 * 512 * 512];
__device__ __align__(16) float g_pyr3[3 * 256 * 256];
__device__ __align__(16) float g_pyr4[3 * 128 * 128];
__device__ __align__(16) float g_pyr5[3 * 64 * 64];
__device__ __align__(16) float g_E2[3 * 1024 * 1024];
__device__ __align__(16) float g_E3[3 * 1024 * 1024];
__device__ __align__(16) float g_E4[3 * 1024 * 1024];
__device__ __align__(16) float g_E5[3 * 1024 * 1024];
__device__ __align__(16) float g_t3a[3 * 512 * 512];
__device__ __align__(16) float g_t4a[3 * 256 * 256];
__device__ __align__(16) float g_t4b[3 * 512 * 512];
__device__ __align__(16) float g_t5a[3 * 128 * 128];
__device__ __align__(16) float g_t5b[3 * 256 * 256];
__device__ __align__(16) float g_t5c[3 * 512 * 512];

// ---------------- fused blur (separable 3-tap) + 2x2 mean downsample ------
__global__ void blur_down_kernel(const float* __restrict__ in, float* __restrict__ out,
                                 int no, float De, float Dm) {
    int x = blockIdx.x * blockDim.x + threadIdx.x;
    int y = blockIdx.y * blockDim.y + threadIdx.y;
    int c = blockIdx.z;
    if (x >= no || y >= no) return;
    int ni = 2 * no;
    const float2* ip = (const float2*)(in) + (size_t)c * ni * no;
    float acc = 0.f;
#pragma unroll
    for (int j = 0; j < 4; j++) {
        int r = 2 * y - 1 + j;
        if (r < 0 || r >= ni) continue;
        const float2* row = ip + (size_t)r * no;
        float2 Bc = row[x];
        float a = (x > 0) ? row[x - 1].y : 0.f;
        float d = (x < no - 1) ? row[x + 1].x : 0.f;
        float wj = (j == 0 || j == 3) ? De : Dm;
        acc += wj * (De * a + Dm * Bc.x + Dm * Bc.y + De * d);
    }
    out[(size_t)c * no * no + (size_t)y * no + x] = acc;
}

// ---------------- composite (bilinear x2 upsample -> 3-tap blur) weights ---
__device__ __forceinline__ void ub_weights(int o, int n, float w0, float w1,
                                           int& base, float w[3]) {
    base = (o >> 1) - 1;
    w[0] = w[1] = w[2] = 0.f;
    int n2 = n * 2;
#pragma unroll
    for (int d = -1; d <= 1; ++d) {
        int p = o + d;
        if (p < 0 || p >= n2) continue;
        float bw = (d == 0) ? w0 : w1;
        int i = p >> 1;
        if ((p & 1) == 0) {
            w[i - 1 - base] += 0.25f * bw;
            w[i - base]     += 0.75f * bw;
        } else {
            w[i - base]     += 0.75f * bw;
            w[i + 1 - base] += 0.25f * bw;
        }
    }
}

// per-pixel up+blur (general path, handles borders/clamping)
__device__ float up_pixel(const float* __restrict__ E, int n, int ox, int oy,
                          float w0, float w1) {
    int by, bx;
    float wy[3], wx[3];
    ub_weights(oy, n, w0, w1, by, wy);
    ub_weights(ox, n, w0, w1, bx, wx);
    int ry[3], rx[3];
#pragma unroll
    for (int j = 0; j < 3; j++) {
        ry[j] = min(max(by + j, 0), n - 1);
        rx[j] = min(max(bx + j, 0), n - 1);
    }
    float s = 0.f;
#pragma unroll
    for (int jy = 0; jy < 3; jy++) {
        const float* row = E + (size_t)ry[jy] * n;
        s += wy[jy] * (wx[0] * row[rx[0]] + wx[1] * row[rx[1]] + wx[2] * row[rx[2]]);
    }
    return s;
}

// ---------------- staged up+blur, quad-based ------------------------------
struct UpTasks {
    const float* in[4];
    float* out[4];
    int n[4];
};

__global__ void up_blur_quad_kernel(UpTasks T, float w0, float w1,
                                    float we0, float we1, float we2) {
    int task = blockIdx.z / 3;
    int c = blockIdx.z - task * 3;
    int n = T.n[task];
    int qx = blockIdx.x * blockDim.x + threadIdx.x;
    int qy = blockIdx.y * blockDim.y + threadIdx.y;
    if (qx >= n || qy >= n) return;
    const float* E = T.in[task] + (size_t)c * n * n;
    int no = 2 * n;
    float* op = T.out[task] + (size_t)c * no * no;

    if (qx == 0 || qx == n - 1 || qy == 0 || qy == n - 1) {
#pragma unroll
        for (int py = 0; py < 2; py++)
#pragma unroll
            for (int px = 0; px < 2; px++) {
                int ox = 2 * qx + px, oy = 2 * qy + py;
                op[(size_t)oy * no + ox] = up_pixel(E, n, ox, oy, w0, w1);
            }
        return;
    }

    const float* pc = E + (size_t)(qy - 1) * n + (qx - 1);
    float he[3], ho[3];
#pragma unroll
    for (int j = 0; j < 3; j++) {
        float a = pc[j * n], b = pc[j * n + 1], d = pc[j * n + 2];
        he[j] = we0 * a + we1 * b + we2 * d;
        ho[j] = we2 * a + we1 * b + we0 * d;
    }
    float2 o0, o1;
    o0.x = we0 * he[0] + we1 * he[1] + we2 * he[2];
    o0.y = we0 * ho[0] + we1 * ho[1] + we2 * ho[2];
    o1.x = we2 * he[0] + we1 * he[1] + we0 * he[2];
    o1.y = we2 * ho[0] + we1 * ho[1] + we0 * ho[2];
    *(float2*)(op + (size_t)(2 * qy) * no + 2 * qx) = o0;
    *(float2*)(op + (size_t)(2 * qy + 1) * no + 2 * qx) = o1;
}

// ---------------- blend helpers --------------------------------------------
__device__ __forceinline__ const float* level_ptr(int l, const float* E1, const float* E2,
                                                  const float* E3, const float* E4,
                                                  const float* E5) {
    const float* p = E1;
    p = (l == 2) ? E2 : p;
    p = (l == 3) ? E3 : p;
    p = (l == 4) ? E4 : p;
    p = (l == 5) ? E5 : p;
    return p;
}

__device__ __forceinline__ float blend_B(int l, float R) {
    float sprev = exp2f((float)(l - 3));
    float ap = sprev * R * (1.0f / 0.248f);
    float tp = expf(-(ap * ap) * 3.0f);
    float tc = 0.f;
    if (l < 5) {
        float ac = 2.0f * ap;
        tc = expf(-(ac * ac) * 3.0f);
    }
    return (0.5f - tc) / (tp - tc + 1e-5f);
}

__device__ void pixel_slow(int x, int y, int l, float R,
                           const float* __restrict__ img,
                           const float* __restrict__ E1, const float* __restrict__ E2,
                           const float* __restrict__ E3, const float* __restrict__ E4,
                           const float* __restrict__ E5, float* __restrict__ out,
                           float w0, float w1) {
    int pix = y * WW + x;
    if (l == 0) {
        out[pix] = img[pix];
        out[pix + HWFULL] = img[pix + HWFULL];
        out[pix + 2 * HWFULL] = img[pix + 2 * HWFULL];
        return;
    }
    float B = blend_B(l, R);
    const float* Ecur = level_ptr(l, E1, E2, E3, E4, E5);
    const float* Eprev = level_ptr(l - 1, E1, E2, E3, E4, E5);
#pragma unroll
    for (int c = 0; c < 3; c++) {
        float vc = up_pixel(Ecur + c * NE * NE, NE, x, y, w0, w1);
        float vp = (l == 1) ? img[pix + c * HWFULL]
                            : up_pixel(Eprev + c * NE * NE, NE, x, y, w0, w1);
        out[pix + c * HWFULL] = B * vp + (1.f - B) * vc;
    }
}

__device__ void quad_global(int qx, int qy, int l0, const float B[2][2],
                            const float* __restrict__ img,
                            const float* __restrict__ cur, const float* __restrict__ prv,
                            float* __restrict__ out,
                            float we0, float we1, float we2) {
    int pix0 = (2 * qy) * WW + 2 * qx;
    int wbase = (qy - 1) * NE + (qx - 1);
#pragma unroll
    for (int c = 0; c < 3; c++) {
        const float* pc = cur + c * NE * NE + wbase;
        float he[3], ho[3];
#pragma unroll
        for (int j = 0; j < 3; j++) {
            float a = pc[j * NE], b = pc[j * NE + 1], d = pc[j * NE + 2];
            he[j] = we0 * a + we1 * b + we2 * d;
            ho[j] = we2 * a + we1 * b + we0 * d;
        }
        float vc[2][2];
        vc[0][0] = we0 * he[0] + we1 * he[1] + we2 * he[2];
        vc[0][1] = we0 * ho[0] + we1 * ho[1] + we2 * ho[2];
        vc[1][0] = we2 * he[0] + we1 * he[1] + we0 * he[2];
        vc[1][1] = we2 * ho[0] + we1 * ho[1] + we0 * ho[2];

        float vp[2][2];
        if (l0 == 1) {
            float2 i0 = *(const float2*)(img + pix0 + c * HWFULL);
            float2 i1 = *(const float2*)(img + pix0 + WW + c * HWFULL);
            vp[0][0] = i0.x; vp[0][1] = i0.y; vp[1][0] = i1.x; vp[1][1] = i1.y;
        } else {
            const float* pp = prv + c * NE * NE + wbase;
            float pe[3], po[3];
#pragma unroll
            for (int j = 0; j < 3; j++) {
                float a = pp[j * NE], b = pp[j * NE + 1], d = pp[j * NE + 2];
                pe[j] = we0 * a + we1 * b + we2 * d;
                po[j] = we2 * a + we1 * b + we0 * d;
            }
            vp[0][0] = we0 * pe[0] + we1 * pe[1] + we2 * pe[2];
            vp[0][1] = we0 * po[0] + we1 * po[1] + we2 * po[2];
            vp[1][0] = we2 * pe[0] + we1 * pe[1] + we0 * pe[2];
            vp[1][1] = we2 * po[0] + we1 * po[1] + we0 * po[2];
        }
        float2 o0, o1;
        o0.x = B[0][0] * vp[0][0] + (1.f - B[0][0]) * vc[0][0];
        o0.y = B[0][1] * vp[0][1] + (1.f - B[0][1]) * vc[0][1];
        o1.x = B[1][0] * vp[1][0] + (1.f - B[1][0]) * vc[1][0];
        o1.y = B[1][1] * vp[1][1] + (1.f - B[1][1]) * vc[1][1];
        *(float2*)(out + pix0 + c * HWFULL) = o0;
        *(float2*)(out + pix0 + WW + c * HWFULL) = o1;
    }
}

// ---------------- blend: block-uniform smem fast path ----------------------
#define TQX 32
#define TQY 8
#define TPITCH 34
#define TROWS 10

__global__ __launch_bounds__(256, 4)
void blend_quad_kernel(const float* __restrict__ img, const float* __restrict__ fixs,
                       const float* __restrict__ E1, const float* __restrict__ E2,
                       const float* __restrict__ E3, const float* __restrict__ E4,
                       const float* __restrict__ E5, float* __restrict__ out,
                       float w0, float w1, float we0, float we1, float we2,
                       float om0, float om1, float om2, float om3, float om4) {
    __shared__ float s_cur[3][TROWS][TPITCH];
    __shared__ float s_prv[3][TROWS][TPITCH];
    __shared__ int s_ref;

    int tx = threadIdx.x, ty = threadIdx.y;
    int qx = blockIdx.x * TQX + tx;
    int qy = blockIdx.y * TQY + ty;

    // per-pixel min squared distance over 4 fixations (incremental within quad)
    float d2q[2][2] = {{3.4e38f, 3.4e38f}, {3.4e38f, 3.4e38f}};
    float x0 = (float)(2 * qx), y0 = (float)(2 * qy);
#pragma unroll
    for (int k = 0; k < 4; k++) {
        float dx = x0 - fixs[2 * k];
        float dy = y0 - fixs[2 * k + 1];
        float d00 = dx * dx + dy * dy;
        float tX = 2.f * dx + 1.f;
        float tY = 2.f * dy + 1.f;
        float d01 = d00 + tX;
        d2q[0][0] = fminf(d2q[0][0], d00);
        d2q[0][1] = fminf(d2q[0][1], d01);
        d2q[1][0] = fminf(d2q[1][0], d00 + tY);
        d2q[1][1] = fminf(d2q[1][1], d01 + tY);
    }

    int lv[2][2];
    float Rv[2][2];
#pragma unroll
    for (int py = 0; py < 2; py++)
#pragma unroll
        for (int px = 0; px < 2; px++) {
            float theta = sqrtf(d2q[py][px]) * (1.0f / 7.5f);
            float R = 2.5f / (theta + 2.5f);
            Rv[py][px] = R;
            // band index == count of omega thresholds >= R (tie goes to deeper band)
            lv[py][px] = (R <= om0) + (R <= om1) + (R <= om2) +
                         (R <= om3) + (R <= om4);
        }

    if (tx == 0 && ty == 0) s_ref = lv[0][0];
    __syncthreads();
    int lref = s_ref;
    bool mine_uniform = (lv[0][0] == lref) && (lv[0][1] == lref) &&
                        (lv[1][0] == lref) && (lv[1][1] == lref);
    int all_uni = __syncthreads_and(mine_uniform ? 1 : 0);
    bool block_border = (blockIdx.x == 0) || (blockIdx.x == gridDim.x - 1) ||
                        (blockIdx.y == 0) || (blockIdx.y == gridDim.y - 1);

    int pix0 = (2 * qy) * WW + 2 * qx;

    if (all_uni && !block_border) {
        if (lref == 0) {
#pragma unroll
            for (int c = 0; c < 3; c++) {
                *(float2*)(out + pix0 + c * HWFULL) =
                    *(const float2*)(img + pix0 + c * HWFULL);
                *(float2*)(out + pix0 + WW + c * HWFULL) =
                    *(const float2*)(img + pix0 + WW + c * HWFULL);
            }
            return;
        }
        const float* cur = level_ptr(lref, E1, E2, E3, E4, E5);
        const float* prv = level_ptr(lref - 1, E1, E2, E3, E4, E5);
        int ox0 = blockIdx.x * TQX - 1;
        int oy0 = blockIdx.y * TQY - 1;
        int tid = ty * TQX + tx;
        int nfill = 3 * TROWS * TPITCH;
        for (int i = tid; i < nfill; i += 256) {
            int c = i / (TROWS * TPITCH);
            int rem = i - c * (TROWS * TPITCH);
            int r = rem / TPITCH, col = rem - r * TPITCH;
            size_t g = (size_t)c * NE * NE + (size_t)(oy0 + r) * NE + (ox0 + col);
            s_cur[c][r][col] = cur[g];
            if (lref >= 2) s_prv[c][r][col] = prv[g];
        }
        __syncthreads();

        float B[2][2];
#pragma unroll
        for (int py = 0; py < 2; py++)
#pragma unroll
            for (int px = 0; px < 2; px++)
                B[py][px] = blend_B(lref, Rv[py][px]);

#pragma unroll
        for (int c = 0; c < 3; c++) {
            float he[3], ho[3];
#pragma unroll
            for (int j = 0; j < 3; j++) {
                float a = s_cur[c][ty + j][tx];
                float b = s_cur[c][ty + j][tx + 1];
                float d = s_cur[c][ty + j][tx + 2];
                he[j] = we0 * a + we1 * b + we2 * d;
                ho[j] = we2 * a + we1 * b + we0 * d;
            }
            float vc[2][2];
            vc[0][0] = we0 * he[0] + we1 * he[1] + we2 * he[2];
            vc[0][1] = we0 * ho[0] + we1 * ho[1] + we2 * ho[2];
            vc[1][0] = we2 * he[0] + we1 * he[1] + we0 * he[2];
            vc[1][1] = we2 * ho[0] + we1 * ho[1] + we0 * ho[2];

            float vp[2][2];
            if (lref == 1) {
                float2 i0 = *(const float2*)(img + pix0 + c * HWFULL);
                float2 i1 = *(const float2*)(img + pix0 + WW + c * HWFULL);
                vp[0][0] = i0.x; vp[0][1] = i0.y; vp[1][0] = i1.x; vp[1][1] = i1.y;
            } else {
                float pe[3], po[3];
#pragma unroll
                for (int j = 0; j < 3; j++) {
                    float a = s_prv[c][ty + j][tx];
                    float b = s_prv[c][ty + j][tx + 1];
                    float d = s_prv[c][ty + j][tx + 2];
                    pe[j] = we0 * a + we1 * b + we2 * d;
                    po[j] = we2 * a + we1 * b + we0 * d;
                }
                vp[0][0] = we0 * pe[0] + we1 * pe[1] + we2 * pe[2];
                vp[0][1] = we0 * po[0] + we1 * po[1] + we2 * po[2];
                vp[1][0] = we2 * pe[0] + we1 * pe[1] + we0 * pe[2];
                vp[1][1] = we2 * po[0] + we1 * po[1] + we0 * po[2];
            }
            float2 o0, o1;
            o0.x = B[0][0] * vp[0][0] + (1.f - B[0][0]) * vc[0][0];
            o0.y = B[0][1] * vp[0][1] + (1.f - B[0][1]) * vc[0][1];
            o1.x = B[1][0] * vp[1][0] + (1.f - B[1][0]) * vc[1][0];
            o1.y = B[1][1] * vp[1][1] + (1.f - B[1][1]) * vc[1][1];
            *(float2*)(out + pix0 + c * HWFULL) = o0;
            *(float2*)(out + pix0 + WW + c * HWFULL) = o1;
        }
        return;
    }

    // fallback paths
    int l0 = lv[0][0];
    bool uni = (lv[0][1] == l0) && (lv[1][0] == l0) && (lv[1][1] == l0);
    bool qborder = (qx == 0) | (qx >= NE - 1) | (qy == 0) | (qy >= NE - 1);

    if (uni && l0 == 0) {
#pragma unroll
        for (int c = 0; c < 3; c++) {
            *(float2*)(out + pix0 + c * HWFULL) =
                *(const float2*)(img + pix0 + c * HWFULL);
            *(float2*)(out + pix0 + WW + c * HWFULL) =
                *(const float2*)(img + pix0 + WW + c * HWFULL);
        }
        return;
    }
    if (!uni || qborder) {
#pragma unroll
        for (int py = 0; py < 2; py++)
#pragma unroll
            for (int px = 0; px < 2; px++)
                pixel_slow(2 * qx + px, 2 * qy + py, lv[py][px], Rv[py][px],
                           img, E1, E2, E3, E4, E5, out, w0, w1);
        return;
    }
    float B[2][2];
#pragma unroll
    for (int py = 0; py < 2; py++)
#pragma unroll
        for (int px = 0; px < 2; px++)
            B[py][px] = blend_B(l0, Rv[py][px]);
    const float* cur = level_ptr(l0, E1, E2, E3, E4, E5);
    const float* prv = level_ptr(l0 - 1, E1, E2, E3, E4, E5);
    quad_global(qx, qy, l0, B, img, cur, prv, out, we0, we1, we2);
}

// ---------------- host launch ---------------------------------------------
extern "C" void kernel_launch(void* const* d_in, const int* in_sizes, int n_in,
                              void* d_out, int out_size) {
    const float* img = (const float*)d_in[0];
    const float* fixs = (const float*)d_in[1];
    float* out = (float*)d_out;

    float *pyr1, *pyr2, *pyr3, *pyr4, *pyr5, *E2, *E3, *E4, *E5;
    float *t3a, *t4a, *t4b, *t5a, *t5b, *t5c;
    cudaGetSymbolAddress((void**)&pyr1, g_pyr1);
    cudaGetSymbolAddress((void**)&pyr2, g_pyr2);
    cudaGetSymbolAddress((void**)&pyr3, g_pyr3);
    cudaGetSymbolAddress((void**)&pyr4, g_pyr4);
    cudaGetSymbolAddress((void**)&pyr5, g_pyr5);
    cudaGetSymbolAddress((void**)&E2, g_E2);
    cudaGetSymbolAddress((void**)&E3, g_E3);
    cudaGetSymbolAddress((void**)&E4, g_E4);
    cudaGetSymbolAddress((void**)&E5, g_E5);
    cudaGetSymbolAddress((void**)&t3a, g_t3a);
    cudaGetSymbolAddress((void**)&t4a, g_t4a);
    cudaGetSymbolAddress((void**)&t4b, g_t4b);
    cudaGetSymbolAddress((void**)&t5a, g_t5a);
    cudaGetSymbolAddress((void**)&t5b, g_t5b);
    cudaGetSymbolAddress((void**)&t5c, g_t5c);

    // Gaussian taps (w2 ~ 7.5e-15 dropped from taps; kept in normalization)
    double s2 = 2.0 * 0.248 * 0.248;
    double g1 = exp(-1.0 / s2);
    double g2 = exp(-4.0 / s2);
    double nrm = 1.0 + 2.0 * g1 + 2.0 * g2;
    float w0 = (float)(1.0 / nrm);
    float w1 = (float)(g1 / nrm);
    float De = (float)(0.5 * g1 / nrm);
    float Dm = (float)(0.5 * (1.0 + g1) / nrm);
    float we0 = 0.25f * w0 + 0.75f * w1;
    float we1 = 0.75f * w0 + w1;
    float we2 = 0.25f * w1;

    double ob = sqrt(log(2.0) / 3.0) * 0.248;
    float om0 = (float)(ob * 4.0);
    float om1 = (float)(ob * 2.0);
    float om2 = (float)(ob);
    float om3 = (float)(ob * 0.5);
    float om4 = (float)(ob * 0.25);

    dim3 blk(32, 8);
    auto grd = [](int n) { return dim3((n + 31) / 32, (n + 7) / 8, 3); };

    // Gaussian pyramid (fused blur + 2x2 mean, float2-coalesced)
    blur_down_kernel<<<grd(1024), blk>>>(img,  pyr1, 1024, De, Dm);
    blur_down_kernel<<<grd(512),  blk>>>(pyr1, pyr2, 512,  De, Dm);
    blur_down_kernel<<<grd(256),  blk>>>(pyr2, pyr3, 256,  De, Dm);
    blur_down_kernel<<<grd(128),  blk>>>(pyr3, pyr4, 128,  De, Dm);
    blur_down_kernel<<<grd(64),   blk>>>(pyr4, pyr5, 64,   De, Dm);

    // Expansion chains to 1024x1024 (E maps), staged, quad-based
    UpTasks A; A.in[0] = pyr2; A.out[0] = E2;  A.n[0] = 512;
               A.in[1] = pyr3; A.out[1] = t3a; A.n[1] = 256;
               A.in[2] = pyr4; A.out[2] = t4a; A.n[2] = 128;
               A.in[3] = pyr5; A.out[3] = t5a; A.n[3] = 64;
    up_blur_quad_kernel<<<dim3(16, 64, 12), blk>>>(A, w0, w1, we0, we1, we2);

    UpTasks B; B.in[0] = t3a; B.out[0] = E3;  B.n[0] = 512;
               B.in[1] = t4a; B.out[1] = t4b; B.n[1] = 256;
               B.in[2] = t5a; B.out[2] = t5b; B.n[2] = 128;
               B.in[3] = 0;   B.out[3] = 0;   B.n[3] = 1;
    up_blur_quad_kernel<<<dim3(16, 64, 9), blk>>>(B, w0, w1, we0, we1, we2);

    UpTasks C; C.in[0] = t4b; C.out[0] = E4;  C.n[0] = 512;
               C.in[1] = t5b; C.out[1] = t5c; C.n[1] = 256;
               C.in[2] = 0;   C.out[2] = 0;   C.n[2] = 1;
               C.in[3] = 0;   C.out[3] = 0;   C.n[3] = 1;
    up_blur_quad_kernel<<<dim3(16, 64, 6), blk>>>(C, w0, w1, we0, we1, we2);

    UpTasks D; D.in[0] = t5c; D.out[0] = E5;  D.n[0] = 512;
               D.in[1] = 0;   D.out[1] = 0;   D.n[1] = 1;
               D.in[2] = 0;   D.out[2] = 0;   D.n[2] = 1;
               D.in[3] = 0;   D.out[3] = 0;   D.n[3] = 1;
    up_blur_quad_kernel<<<dim3(16, 64, 3), blk>>>(D, w0, w1, we0, we1, we2);

    // Final blend, block-uniform smem fast path
    blend_quad_kernel<<<dim3(NE / 32, NE / 8), blk>>>(img, fixs, pyr1, E2, E3, E4, E5,
                                                      out, w0, w1, we0, we1, we2,
                                                      om0, om1, om2, om3, om4);
}

// round 6
// speedup vs baseline: 1.7950x; 1.1216x over previous
#include <cuda_runtime.h>
#include <math.h>

#define HH 2048
#define WW 2048
#define HWFULL (HH * WW)
#define NE 1024              // E maps (half-res expansions) are 1024x1024

// ---------------- static scratch (no allocations allowed) ----------------
__device__ __align__(16) float g_pyr1[3 * 1024 * 1024];
__device__ __align__(16) float g_pyr2[3 * 512 * 512];
__device__ __align__(16) float g_pyr3[3 * 256 * 256];
__device__ __align__(16) float g_pyr4[3 * 128 * 128];
__device__ __align__(16) float g_pyr5[3 * 64 * 64];
__device__ __align__(16) float g_E2[3 * 1024 * 1024];
__device__ __align__(16) float g_E3[3 * 1024 * 1024];
__device__ __align__(16) float g_E4[3 * 1024 * 1024];
__device__ __align__(16) float g_E5[3 * 1024 * 1024];
__device__ __align__(16) float g_t3a[3 * 512 * 512];
__device__ __align__(16) float g_t4a[3 * 256 * 256];
__device__ __align__(16) float g_t4b[3 * 512 * 512];
__device__ __align__(16) float g_t5a[3 * 128 * 128];
__device__ __align__(16) float g_t5b[3 * 256 * 256];
__device__ __align__(16) float g_t5c[3 * 512 * 512];

// ---------------- fused blur (separable 3-tap) + 2x2 mean downsample ------
__global__ void blur_down_kernel(const float* __restrict__ in, float* __restrict__ out,
                                 int no, float De, float Dm) {
    int x = blockIdx.x * blockDim.x + threadIdx.x;
    int y = blockIdx.y * blockDim.y + threadIdx.y;
    int c = blockIdx.z;
    if (x >= no || y >= no) return;
    int ni = 2 * no;
    const float2* ip = (const float2*)(in) + (size_t)c * ni * no;
    float acc = 0.f;
#pragma unroll
    for (int j = 0; j < 4; j++) {
        int r = 2 * y - 1 + j;
        if (r < 0 || r >= ni) continue;
        const float2* row = ip + (size_t)r * no;
        float2 Bc = row[x];
        float a = (x > 0) ? row[x - 1].y : 0.f;
        float d = (x < no - 1) ? row[x + 1].x : 0.f;
        float wj = (j == 0 || j == 3) ? De : Dm;
        acc += wj * (De * a + Dm * Bc.x + Dm * Bc.y + De * d);
    }
    out[(size_t)c * no * no + (size_t)y * no + x] = acc;
}

// ---------------- fused small down chain: pyr2 -> pyr3,pyr4,pyr5 ----------
__device__ __forceinline__ void dstage(const float* __restrict__ sin, int pin,
                                       float* __restrict__ sout, int so,
                                       int offR, int offC, int n,
                                       float De, float Dm, int tid) {
    for (int i = tid; i < so * so; i += 256) {
        int v = i / so, u = i - v * so;
        int gy = offR + v, gx = offC + u;
        float val = 0.f;
        if (gy >= 0 && gy < n && gx >= 0 && gx < n) {
            float acc = 0.f;
#pragma unroll
            for (int j = 0; j < 4; j++) {
                const float* row = sin + (2 * v + j) * pin + 2 * u;
                float wj = (j == 0 || j == 3) ? De : Dm;
                acc += wj * (De * row[0] + Dm * row[1] + Dm * row[2] + De * row[3]);
            }
            val = acc;
        }
        sout[i] = val;
    }
}

__global__ __launch_bounds__(256)
void down_small_kernel(const float* __restrict__ pyr2,
                       float* __restrict__ pyr3, float* __restrict__ pyr4,
                       float* __restrict__ pyr5, float De, float Dm) {
    __shared__ float s2[78 * 78];
    __shared__ float s3[38 * 38];
    __shared__ float s4[18 * 18];
    int bx = blockIdx.x, by = blockIdx.y, c = blockIdx.z;
    int tid = threadIdx.x;

    const float* p2 = pyr2 + (size_t)c * 512 * 512;
    int r0 = 64 * by - 7, c0 = 64 * bx - 7;
    for (int i = tid; i < 78 * 78; i += 256) {
        int v = i / 78, u = i - v * 78;
        int gr = r0 + v, gc = c0 + u;
        float val = 0.f;
        if (gr >= 0 && gr < 512 && gc >= 0 && gc < 512)
            val = p2[(size_t)gr * 512 + gc];
        s2[i] = val;
    }
    __syncthreads();

    dstage(s2, 78, s3, 38, 32 * by - 3, 32 * bx - 3, 256, De, Dm, tid);
    __syncthreads();
    dstage(s3, 38, s4, 18, 16 * by - 1, 16 * bx - 1, 128, De, Dm, tid);
    __syncthreads();

    float* p3 = pyr3 + (size_t)c * 256 * 256;
    for (int i = tid; i < 32 * 32; i += 256) {
        int v = i >> 5, u = i & 31;
        p3[(size_t)(32 * by + v) * 256 + 32 * bx + u] = s3[(v + 3) * 38 + u + 3];
    }
    float* p4 = pyr4 + (size_t)c * 128 * 128;
    for (int i = tid; i < 16 * 16; i += 256) {
        int v = i >> 4, u = i & 15;
        p4[(size_t)(16 * by + v) * 128 + 16 * bx + u] = s4[(v + 1) * 18 + u + 1];
    }
    float* p5 = pyr5 + (size_t)c * 64 * 64;
    for (int i = tid; i < 8 * 8; i += 256) {
        int v = i >> 3, u = i & 7;
        float acc = 0.f;
#pragma unroll
        for (int j = 0; j < 4; j++) {
            const float* row = s4 + (2 * v + j) * 18 + 2 * u;
            float wj = (j == 0 || j == 3) ? De : Dm;
            acc += wj * (De * row[0] + Dm * row[1] + Dm * row[2] + De * row[3]);
        }
        p5[(size_t)(8 * by + v) * 64 + 8 * bx + u] = acc;
    }
}

// ---------------- composite (bilinear x2 upsample -> 3-tap blur) weights ---
__device__ __forceinline__ void ub_weights(int o, int n, float w0, float w1,
                                           int& base, float w[3]) {
    base = (o >> 1) - 1;
    w[0] = w[1] = w[2] = 0.f;
    int n2 = n * 2;
#pragma unroll
    for (int d = -1; d <= 1; ++d) {
        int p = o + d;
        if (p < 0 || p >= n2) continue;
        float bw = (d == 0) ? w0 : w1;
        int i = p >> 1;
        if ((p & 1) == 0) {
            w[i - 1 - base] += 0.25f * bw;
            w[i - base]     += 0.75f * bw;
        } else {
            w[i - base]     += 0.75f * bw;
            w[i + 1 - base] += 0.25f * bw;
        }
    }
}

__device__ float up_pixel(const float* __restrict__ E, int n, int ox, int oy,
                          float w0, float w1) {
    int by, bx;
    float wy[3], wx[3];
    ub_weights(oy, n, w0, w1, by, wy);
    ub_weights(ox, n, w0, w1, bx, wx);
    int ry[3], rx[3];
#pragma unroll
    for (int j = 0; j < 3; j++) {
        ry[j] = min(max(by + j, 0), n - 1);
        rx[j] = min(max(bx + j, 0), n - 1);
    }
    float s = 0.f;
#pragma unroll
    for (int jy = 0; jy < 3; jy++) {
        const float* row = E + (size_t)ry[jy] * n;
        s += wy[jy] * (wx[0] * row[rx[0]] + wx[1] * row[rx[1]] + wx[2] * row[rx[2]]);
    }
    return s;
}

// ---------------- staged up+blur, quad-based ------------------------------
struct UpTasks {
    const float* in[4];
    float* out[4];
    int n[4];
};

__global__ void up_blur_quad_kernel(UpTasks T, float w0, float w1,
                                    float we0, float we1, float we2) {
    int task = blockIdx.z / 3;
    int c = blockIdx.z - task * 3;
    int n = T.n[task];
    int qx = blockIdx.x * blockDim.x + threadIdx.x;
    int qy = blockIdx.y * blockDim.y + threadIdx.y;
    if (qx >= n || qy >= n) return;
    const float* E = T.in[task] + (size_t)c * n * n;
    int no = 2 * n;
    float* op = T.out[task] + (size_t)c * no * no;

    if (qx == 0 || qx == n - 1 || qy == 0 || qy == n - 1) {
#pragma unroll
        for (int py = 0; py < 2; py++)
#pragma unroll
            for (int px = 0; px < 2; px++) {
                int ox = 2 * qx + px, oy = 2 * qy + py;
                op[(size_t)oy * no + ox] = up_pixel(E, n, ox, oy, w0, w1);
            }
        return;
    }

    const float* pc = E + (size_t)(qy - 1) * n + (qx - 1);
    float he[3], ho[3];
#pragma unroll
    for (int j = 0; j < 3; j++) {
        float a = pc[j * n], b = pc[j * n + 1], d = pc[j * n + 2];
        he[j] = we0 * a + we1 * b + we2 * d;
        ho[j] = we2 * a + we1 * b + we0 * d;
    }
    float2 o0, o1;
    o0.x = we0 * he[0] + we1 * he[1] + we2 * he[2];
    o0.y = we0 * ho[0] + we1 * ho[1] + we2 * ho[2];
    o1.x = we2 * he[0] + we1 * he[1] + we0 * he[2];
    o1.y = we2 * ho[0] + we1 * ho[1] + we0 * ho[2];
    *(float2*)(op + (size_t)(2 * qy) * no + 2 * qx) = o0;
    *(float2*)(op + (size_t)(2 * qy + 1) * no + 2 * qx) = o1;
}

// ---------------- blend helpers --------------------------------------------
__device__ __forceinline__ const float* level_ptr(int l, const float* E1, const float* E2,
                                                  const float* E3, const float* E4,
                                                  const float* E5) {
    const float* p = E1;
    p = (l == 2) ? E2 : p;
    p = (l == 3) ? E3 : p;
    p = (l == 4) ? E4 : p;
    p = (l == 5) ? E5 : p;
    return p;
}

__device__ __forceinline__ float blend_B(int l, float R) {
    float sprev = exp2f((float)(l - 3));
    float ap = sprev * R * (1.0f / 0.248f);
    float tp = expf(-(ap * ap) * 3.0f);
    float tc = 0.f;
    if (l < 5) {
        float ac = 2.0f * ap;
        tc = expf(-(ac * ac) * 3.0f);
    }
    return (0.5f - tc) / (tp - tc + 1e-5f);
}

__device__ void pixel_slow(int x, int y, int l, float R,
                           const float* __restrict__ img,
                           const float* __restrict__ E1, const float* __restrict__ E2,
                           const float* __restrict__ E3, const float* __restrict__ E4,
                           const float* __restrict__ E5, float* __restrict__ out,
                           float w0, float w1) {
    int pix = y * WW + x;
    if (l == 0) {
        out[pix] = img[pix];
        out[pix + HWFULL] = img[pix + HWFULL];
        out[pix + 2 * HWFULL] = img[pix + 2 * HWFULL];
        return;
    }
    float B = blend_B(l, R);
    const float* Ecur = level_ptr(l, E1, E2, E3, E4, E5);
    const float* Eprev = level_ptr(l - 1, E1, E2, E3, E4, E5);
#pragma unroll
    for (int c = 0; c < 3; c++) {
        float vc = up_pixel(Ecur + c * NE * NE, NE, x, y, w0, w1);
        float vp = (l == 1) ? img[pix + c * HWFULL]
                            : up_pixel(Eprev + c * NE * NE, NE, x, y, w0, w1);
        out[pix + c * HWFULL] = B * vp + (1.f - B) * vc;
    }
}

__device__ void quad_global(int qx, int qy, int l0, const float B[2][2],
                            const float* __restrict__ img,
                            const float* __restrict__ cur, const float* __restrict__ prv,
                            float* __restrict__ out,
                            float we0, float we1, float we2) {
    int pix0 = (2 * qy) * WW + 2 * qx;
    int wbase = (qy - 1) * NE + (qx - 1);
#pragma unroll
    for (int c = 0; c < 3; c++) {
        const float* pc = cur + c * NE * NE + wbase;
        float he[3], ho[3];
#pragma unroll
        for (int j = 0; j < 3; j++) {
            float a = pc[j * NE], b = pc[j * NE + 1], d = pc[j * NE + 2];
            he[j] = we0 * a + we1 * b + we2 * d;
            ho[j] = we2 * a + we1 * b + we0 * d;
        }
        float vc[2][2];
        vc[0][0] = we0 * he[0] + we1 * he[1] + we2 * he[2];
        vc[0][1] = we0 * ho[0] + we1 * ho[1] + we2 * ho[2];
        vc[1][0] = we2 * he[0] + we1 * he[1] + we0 * he[2];
        vc[1][1] = we2 * ho[0] + we1 * ho[1] + we0 * ho[2];

        float vp[2][2];
        if (l0 == 1) {
            float2 i0 = *(const float2*)(img + pix0 + c * HWFULL);
            float2 i1 = *(const float2*)(img + pix0 + WW + c * HWFULL);
            vp[0][0] = i0.x; vp[0][1] = i0.y; vp[1][0] = i1.x; vp[1][1] = i1.y;
        } else {
            const float* pp = prv + c * NE * NE + wbase;
            float pe[3], po[3];
#pragma unroll
            for (int j = 0; j < 3; j++) {
                float a = pp[j * NE], b = pp[j * NE + 1], d = pp[j * NE + 2];
                pe[j] = we0 * a + we1 * b + we2 * d;
                po[j] = we2 * a + we1 * b + we0 * d;
            }
            vp[0][0] = we0 * pe[0] + we1 * pe[1] + we2 * pe[2];
            vp[0][1] = we0 * po[0] + we1 * po[1] + we2 * po[2];
            vp[1][0] = we2 * pe[0] + we1 * pe[1] + we0 * pe[2];
            vp[1][1] = we2 * po[0] + we1 * po[1] + we0 * po[2];
        }
        float2 o0, o1;
        o0.x = B[0][0] * vp[0][0] + (1.f - B[0][0]) * vc[0][0];
        o0.y = B[0][1] * vp[0][1] + (1.f - B[0][1]) * vc[0][1];
        o1.x = B[1][0] * vp[1][0] + (1.f - B[1][0]) * vc[1][0];
        o1.y = B[1][1] * vp[1][1] + (1.f - B[1][1]) * vc[1][1];
        *(float2*)(out + pix0 + c * HWFULL) = o0;
        *(float2*)(out + pix0 + WW + c * HWFULL) = o1;
    }
}

// ---------------- blend: smem fast path covering 1- and 2-level blocks -----
#define TQX 32
#define TQY 8
#define TPITCH 34
#define TROWS 10

// per-pixel eval from a staged smem window with parity-selected weights
__device__ __forceinline__ float evalw(const float w[TROWS][TPITCH], int ty, int tx,
                                       int oxo, int oyo,
                                       float we0, float we1, float we2) {
    float h[3];
#pragma unroll
    for (int j = 0; j < 3; j++) {
        float a = w[ty + j][tx], b = w[ty + j][tx + 1], d = w[ty + j][tx + 2];
        h[j] = oxo ? (we2 * a + we1 * b + we0 * d) : (we0 * a + we1 * b + we2 * d);
    }
    return oyo ? (we2 * h[0] + we1 * h[1] + we0 * h[2])
               : (we0 * h[0] + we1 * h[1] + we2 * h[2]);
}

__global__ __launch_bounds__(256, 4)
void blend_quad_kernel(const float* __restrict__ img, const float* __restrict__ fixs,
                       const float* __restrict__ E1, const float* __restrict__ E2,
                       const float* __restrict__ E3, const float* __restrict__ E4,
                       const float* __restrict__ E5, float* __restrict__ out,
                       float w0, float w1, float we0, float we1, float we2,
                       float om0, float om1, float om2, float om3, float om4) {
    __shared__ float s_w[3][3][TROWS][TPITCH];   // slot, channel, row, col
    __shared__ int s_mask;

    int tx = threadIdx.x, ty = threadIdx.y;
    int qx = blockIdx.x * TQX + tx;
    int qy = blockIdx.y * TQY + ty;
    int tid = ty * TQX + tx;

    // min squared distance over 4 fixations (incremental within quad)
    float d2q[2][2] = {{3.4e38f, 3.4e38f}, {3.4e38f, 3.4e38f}};
    float x0 = (float)(2 * qx), y0 = (float)(2 * qy);
#pragma unroll
    for (int k = 0; k < 4; k++) {
        float dx = x0 - fixs[2 * k];
        float dy = y0 - fixs[2 * k + 1];
        float d00 = dx * dx + dy * dy;
        float tX = 2.f * dx + 1.f;
        float tY = 2.f * dy + 1.f;
        float d01 = d00 + tX;
        d2q[0][0] = fminf(d2q[0][0], d00);
        d2q[0][1] = fminf(d2q[0][1], d01);
        d2q[1][0] = fminf(d2q[1][0], d00 + tY);
        d2q[1][1] = fminf(d2q[1][1], d01 + tY);
    }

    int lv[2][2];
    float Rv[2][2];
#pragma unroll
    for (int py = 0; py < 2; py++)
#pragma unroll
        for (int px = 0; px < 2; px++) {
            float theta = sqrtf(d2q[py][px]) * (1.0f / 7.5f);
            float R = 2.5f / (theta + 2.5f);
            Rv[py][px] = R;
            lv[py][px] = (R <= om0) + (R <= om1) + (R <= om2) +
                         (R <= om3) + (R <= om4);
        }

    // block-level level bitmask
    if (tid == 0) s_mask = 0;
    __syncthreads();
    int myMask = (1 << lv[0][0]) | (1 << lv[0][1]) | (1 << lv[1][0]) | (1 << lv[1][1]);
    atomicOr(&s_mask, myMask);
    __syncthreads();
    int mask = s_mask;
    int lmin = __ffs(mask) - 1;
    int lmax = 31 - __clz(mask);
    bool block_border = (blockIdx.x == 0) || (blockIdx.x == gridDim.x - 1) ||
                        (blockIdx.y == 0) || (blockIdx.y == gridDim.y - 1);

    int pix0 = (2 * qy) * WW + 2 * qx;

    if (!block_border && (lmax - lmin) <= 1) {
        if (mask == 1) {   // all level 0: pass-through block
#pragma unroll
            for (int c = 0; c < 3; c++) {
                *(float2*)(out + pix0 + c * HWFULL) =
                    *(const float2*)(img + pix0 + c * HWFULL);
                *(float2*)(out + pix0 + WW + c * HWFULL) =
                    *(const float2*)(img + pix0 + WW + c * HWFULL);
            }
            return;
        }
        int base = max(lmin, 1);
        bool hasP = (base >= 2);
        bool hasN = (lmax > base);
        const float* Ebase = level_ptr(base, E1, E2, E3, E4, E5);
        const float* Eprv = hasP ? level_ptr(base - 1, E1, E2, E3, E4, E5) : Ebase;
        const float* Enxt = hasN ? level_ptr(base + 1, E1, E2, E3, E4, E5) : Ebase;

        int ox0 = blockIdx.x * TQX - 1;
        int oy0 = blockIdx.y * TQY - 1;
        const int NF = 3 * TROWS * TPITCH;   // 1020
        for (int i = tid; i < NF; i += 256) {
            int c = i / (TROWS * TPITCH);
            int rem = i - c * (TROWS * TPITCH);
            int r = rem / TPITCH, col = rem - r * TPITCH;
            size_t g = (size_t)c * NE * NE + (size_t)(oy0 + r) * NE + (ox0 + col);
            s_w[1][c][r][col] = Ebase[g];
            if (hasP) s_w[0][c][r][col] = Eprv[g];
            if (hasN) s_w[2][c][r][col] = Enxt[g];
        }
        __syncthreads();

        int lq = lv[0][0];
        bool uniq = (lv[0][1] == lq) && (lv[1][0] == lq) && (lv[1][1] == lq);

        if (uniq && lq == 0) {
#pragma unroll
            for (int c = 0; c < 3; c++) {
                *(float2*)(out + pix0 + c * HWFULL) =
                    *(const float2*)(img + pix0 + c * HWFULL);
                *(float2*)(out + pix0 + WW + c * HWFULL) =
                    *(const float2*)(img + pix0 + WW + c * HWFULL);
            }
            return;
        }

        if (uniq) {
            int cs = 1 + (lq - base);
            float B[2][2];
#pragma unroll
            for (int py = 0; py < 2; py++)
#pragma unroll
                for (int px = 0; px < 2; px++)
                    B[py][px] = blend_B(lq, Rv[py][px]);

#pragma unroll
            for (int c = 0; c < 3; c++) {
                const float (*wc)[TPITCH] = s_w[cs][c];
                float he[3], ho[3];
#pragma unroll
                for (int j = 0; j < 3; j++) {
                    float a = wc[ty + j][tx], b = wc[ty + j][tx + 1],
                          d = wc[ty + j][tx + 2];
                    he[j] = we0 * a + we1 * b + we2 * d;
                    ho[j] = we2 * a + we1 * b + we0 * d;
                }
                float vc[2][2];
                vc[0][0] = we0 * he[0] + we1 * he[1] + we2 * he[2];
                vc[0][1] = we0 * ho[0] + we1 * ho[1] + we2 * ho[2];
                vc[1][0] = we2 * he[0] + we1 * he[1] + we0 * he[2];
                vc[1][1] = we2 * ho[0] + we1 * ho[1] + we0 * ho[2];

                float vp[2][2];
                if (lq == 1) {
                    float2 i0 = *(const float2*)(img + pix0 + c * HWFULL);
                    float2 i1 = *(const float2*)(img + pix0 + WW + c * HWFULL);
                    vp[0][0] = i0.x; vp[0][1] = i0.y; vp[1][0] = i1.x; vp[1][1] = i1.y;
                } else {
                    const float (*wp)[TPITCH] = s_w[cs - 1][c];
                    float pe[3], po[3];
#pragma unroll
                    for (int j = 0; j < 3; j++) {
                        float a = wp[ty + j][tx], b = wp[ty + j][tx + 1],
                              d = wp[ty + j][tx + 2];
                        pe[j] = we0 * a + we1 * b + we2 * d;
                        po[j] = we2 * a + we1 * b + we0 * d;
                    }
                    vp[0][0] = we0 * pe[0] + we1 * pe[1] + we2 * pe[2];
                    vp[0][1] = we0 * po[0] + we1 * po[1] + we2 * po[2];
                    vp[1][0] = we2 * pe[0] + we1 * pe[1] + we0 * pe[2];
                    vp[1][1] = we2 * po[0] + we1 * po[1] + we0 * po[2];
                }
                float2 o0, o1;
                o0.x = B[0][0] * vp[0][0] + (1.f - B[0][0]) * vc[0][0];
                o0.y = B[0][1] * vp[0][1] + (1.f - B[0][1]) * vc[0][1];
                o1.x = B[1][0] * vp[1][0] + (1.f - B[1][0]) * vc[1][0];
                o1.y = B[1][1] * vp[1][1] + (1.f - B[1][1]) * vc[1][1];
                *(float2*)(out + pix0 + c * HWFULL) = o0;
                *(float2*)(out + pix0 + WW + c * HWFULL) = o1;
            }
            return;
        }

        // mixed quad inside a 2-level block: per-pixel from smem
        float px_out[2][2][3];
#pragma unroll
        for (int py = 0; py < 2; py++)
#pragma unroll
            for (int px = 0; px < 2; px++) {
                int l = lv[py][px];
                int pp = pix0 + py * WW + px;
                if (l == 0) {
#pragma unroll
                    for (int c = 0; c < 3; c++)
                        px_out[py][px][c] = img[pp + c * HWFULL];
                } else {
                    int cs = 1 + (l - base);
                    float B = blend_B(l, Rv[py][px]);
#pragma unroll
                    for (int c = 0; c < 3; c++) {
                        float vc = evalw(s_w[cs][c], ty, tx, px, py, we0, we1, we2);
                        float vp = (l == 1) ? img[pp + c * HWFULL]
                                 : evalw(s_w[cs - 1][c], ty, tx, px, py, we0, we1, we2);
                        px_out[py][px][c] = B * vp + (1.f - B) * vc;
                    }
                }
            }
#pragma unroll
        for (int c = 0; c < 3; c++) {
            float2 o0, o1;
            o0.x = px_out[0][0][c]; o0.y = px_out[0][1][c];
            o1.x = px_out[1][0][c]; o1.y = px_out[1][1][c];
            *(float2*)(out + pix0 + c * HWFULL) = o0;
            *(float2*)(out + pix0 + WW + c * HWFULL) = o1;
        }
        return;
    }

    // ---- fallback: border blocks / >2-level blocks (rare) ----
    int l0 = lv[0][0];
    bool uni = (lv[0][1] == l0) && (lv[1][0] == l0) && (lv[1][1] == l0);
    bool qborder = (qx == 0) | (qx >= NE - 1) | (qy == 0) | (qy >= NE - 1);

    if (uni && l0 == 0) {
#pragma unroll
        for (int c = 0; c < 3; c++) {
            *(float2*)(out + pix0 + c * HWFULL) =
                *(const float2*)(img + pix0 + c * HWFULL);
            *(float2*)(out + pix0 + WW + c * HWFULL) =
                *(const float2*)(img + pix0 + WW + c * HWFULL);
        }
        return;
    }
    if (!uni || qborder) {
#pragma unroll
        for (int py = 0; py < 2; py++)
#pragma unroll
            for (int px = 0; px < 2; px++)
                pixel_slow(2 * qx + px, 2 * qy + py, lv[py][px], Rv[py][px],
                           img, E1, E2, E3, E4, E5, out, w0, w1);
        return;
    }
    float B[2][2];
#pragma unroll
    for (int py = 0; py < 2; py++)
#pragma unroll
        for (int px = 0; px < 2; px++)
            B[py][px] = blend_B(l0, Rv[py][px]);
    const float* cur = level_ptr(l0, E1, E2, E3, E4, E5);
    const float* prv = level_ptr(l0 - 1, E1, E2, E3, E4, E5);
    quad_global(qx, qy, l0, B, img, cur, prv, out, we0, we1, we2);
}

// ---------------- host launch ---------------------------------------------
extern "C" void kernel_launch(void* const* d_in, const int* in_sizes, int n_in,
                              void* d_out, int out_size) {
    const float* img = (const float*)d_in[0];
    const float* fixs = (const float*)d_in[1];
    float* out = (float*)d_out;

    float *pyr1, *pyr2, *pyr3, *pyr4, *pyr5, *E2, *E3, *E4, *E5;
    float *t3a, *t4a, *t4b, *t5a, *t5b, *t5c;
    cudaGetSymbolAddress((void**)&pyr1, g_pyr1);
    cudaGetSymbolAddress((void**)&pyr2, g_pyr2);
    cudaGetSymbolAddress((void**)&pyr3, g_pyr3);
    cudaGetSymbolAddress((void**)&pyr4, g_pyr4);
    cudaGetSymbolAddress((void**)&pyr5, g_pyr5);
    cudaGetSymbolAddress((void**)&E2, g_E2);
    cudaGetSymbolAddress((void**)&E3, g_E3);
    cudaGetSymbolAddress((void**)&E4, g_E4);
    cudaGetSymbolAddress((void**)&E5, g_E5);
    cudaGetSymbolAddress((void**)&t3a, g_t3a);
    cudaGetSymbolAddress((void**)&t4a, g_t4a);
    cudaGetSymbolAddress((void**)&t4b, g_t4b);
    cudaGetSymbolAddress((void**)&t5a, g_t5a);
    cudaGetSymbolAddress((void**)&t5b, g_t5b);
    cudaGetSymbolAddress((void**)&t5c, g_t5c);

    // Gaussian taps (w2 ~ 7.5e-15 dropped from taps; kept in normalization)
    double s2 = 2.0 * 0.248 * 0.248;
    double g1 = exp(-1.0 / s2);
    double g2 = exp(-4.0 / s2);
    double nrm = 1.0 + 2.0 * g1 + 2.0 * g2;
    float w0 = (float)(1.0 / nrm);
    float w1 = (float)(g1 / nrm);
    float De = (float)(0.5 * g1 / nrm);
    float Dm = (float)(0.5 * (1.0 + g1) / nrm);
    float we0 = 0.25f * w0 + 0.75f * w1;
    float we1 = 0.75f * w0 + w1;
    float we2 = 0.25f * w1;

    double ob = sqrt(log(2.0) / 3.0) * 0.248;
    float om0 = (float)(ob * 4.0);
    float om1 = (float)(ob * 2.0);
    float om2 = (float)(ob);
    float om3 = (float)(ob * 0.5);
    float om4 = (float)(ob * 0.25);

    dim3 blk(32, 8);

    // Gaussian pyramid: two big levels + fused small chain
    blur_down_kernel<<<dim3(32, 128, 3), blk>>>(img, pyr1, 1024, De, Dm);
    blur_down_kernel<<<dim3(16, 64, 3),  blk>>>(pyr1, pyr2, 512, De, Dm);
    down_small_kernel<<<dim3(8, 8, 3), 256>>>(pyr2, pyr3, pyr4, pyr5, De, Dm);

    // Expansion chains to 1024x1024 (E maps), staged, quad-based
    UpTasks A; A.in[0] = pyr2; A.out[0] = E2;  A.n[0] = 512;
               A.in[1] = pyr3; A.out[1] = t3a; A.n[1] = 256;
               A.in[2] = pyr4; A.out[2] = t4a; A.n[2] = 128;
               A.in[3] = pyr5; A.out[3] = t5a; A.n[3] = 64;
    up_blur_quad_kernel<<<dim3(16, 64, 12), blk>>>(A, w0, w1, we0, we1, we2);

    UpTasks B; B.in[0] = t3a; B.out[0] = E3;  B.n[0] = 512;
               B.in[1] = t4a; B.out[1] = t4b; B.n[1] = 256;
               B.in[2] = t5a; B.out[2] = t5b; B.n[2] = 128;
               B.in[3] = 0;   B.out[3] = 0;   B.n[3] = 1;
    up_blur_quad_kernel<<<dim3(16, 64, 9), blk>>>(B, w0, w1, we0, we1, we2);

    UpTasks C; C.in[0] = t4b; C.out[0] = E4;  C.n[0] = 512;
               C.in[1] = t5b; C.out[1] = t5c; C.n[1] = 256;
               C.in[2] = 0;   C.out[2] = 0;   C.n[2] = 1;
               C.in[3] = 0;   C.out[3] = 0;   C.n[3] = 1;
    up_blur_quad_kernel<<<dim3(16, 64, 6), blk>>>(C, w0, w1, we0, we1, we2);

    UpTasks D; D.in[0] = t5c; D.out[0] = E5;  D.n[0] = 512;
               D.in[1] = 0;   D.out[1] = 0;   D.n[1] = 1;
               D.in[2] = 0;   D.out[2] = 0;   D.n[2] = 1;
               D.in[3] = 0;   D.out[3] = 0;   D.n[3] = 1;
    up_blur_quad_kernel<<<dim3(16, 64, 3), blk>>>(D, w0, w1, we0, we1, we2);

    // Final blend
    blend_quad_kernel<<<dim3(NE / 32, NE / 8), blk>>>(img, fixs, pyr1, E2, E3, E4, E5,
                                                      out, w0, w1, we0, we1, we2,
                                                      om0, om1, om2, om3, om4);
}

// round 7
// speedup vs baseline: 2.0716x; 1.1541x over previous
#include <cuda_runtime.h>
#include <math.h>

#define HH 2048
#define WW 2048
#define HWFULL (HH * WW)
#define NE 1024              // E maps (half-res expansions) are 1024x1024

// ---------------- static scratch (no allocations allowed) ----------------
__device__ __align__(16) float g_pyr1[3 * 1024 * 1024];
__device__ __align__(16) float g_pyr2[3 * 512 * 512];
__device__ __align__(16) float g_pyr3[3 * 256 * 256];
__device__ __align__(16) float g_pyr4[3 * 128 * 128];
__device__ __align__(16) float g_pyr5[3 * 64 * 64];
__device__ __align__(16) float g_E2[3 * 1024 * 1024];
__device__ __align__(16) float g_E3[3 * 1024 * 1024];
__device__ __align__(16) float g_E4[3 * 1024 * 1024];
__device__ __align__(16) float g_E5[3 * 1024 * 1024];
__device__ __align__(16) float g_t3a[3 * 512 * 512];
__device__ __align__(16) float g_t4a[3 * 256 * 256];
__device__ __align__(16) float g_t4b[3 * 512 * 512];
__device__ __align__(16) float g_t5a[3 * 128 * 128];
__device__ __align__(16) float g_t5b[3 * 256 * 256];
__device__ __align__(16) float g_t5c[3 * 512 * 512];

// ---------------- fused blur (separable 3-tap) + 2x2 mean downsample ------
__global__ void blur_down_kernel(const float* __restrict__ in, float* __restrict__ out,
                                 int no, float De, float Dm) {
    int x = blockIdx.x * blockDim.x + threadIdx.x;
    int y = blockIdx.y * blockDim.y + threadIdx.y;
    int c = blockIdx.z;
    if (x >= no || y >= no) return;
    int ni = 2 * no;
    const float2* ip = (const float2*)(in) + (size_t)c * ni * no;
    float acc = 0.f;
#pragma unroll
    for (int j = 0; j < 4; j++) {
        int r = 2 * y - 1 + j;
        if (r < 0 || r >= ni) continue;
        const float2* row = ip + (size_t)r * no;
        float2 Bc = row[x];
        float a = (x > 0) ? row[x - 1].y : 0.f;
        float d = (x < no - 1) ? row[x + 1].x : 0.f;
        float wj = (j == 0 || j == 3) ? De : Dm;
        acc += wj * (De * a + Dm * Bc.x + Dm * Bc.y + De * d);
    }
    out[(size_t)c * no * no + (size_t)y * no + x] = acc;
}

// ---------------- fused small down chain: pyr2 -> pyr3,pyr4,pyr5 ----------
__device__ __forceinline__ void dstage(const float* __restrict__ sin, int pin,
                                       float* __restrict__ sout, int so,
                                       int offR, int offC, int n,
                                       float De, float Dm, int tid) {
    for (int i = tid; i < so * so; i += 256) {
        int v = i / so, u = i - v * so;
        int gy = offR + v, gx = offC + u;
        float val = 0.f;
        if (gy >= 0 && gy < n && gx >= 0 && gx < n) {
            float acc = 0.f;
#pragma unroll
            for (int j = 0; j < 4; j++) {
                const float* row = sin + (2 * v + j) * pin + 2 * u;
                float wj = (j == 0 || j == 3) ? De : Dm;
                acc += wj * (De * row[0] + Dm * row[1] + Dm * row[2] + De * row[3]);
            }
            val = acc;
        }
        sout[i] = val;
    }
}

__global__ __launch_bounds__(256)
void down_small_kernel(const float* __restrict__ pyr2,
                       float* __restrict__ pyr3, float* __restrict__ pyr4,
                       float* __restrict__ pyr5, float De, float Dm) {
    __shared__ float s2[78 * 78];
    __shared__ float s3[38 * 38];
    __shared__ float s4[18 * 18];
    int bx = blockIdx.x, by = blockIdx.y, c = blockIdx.z;
    int tid = threadIdx.x;

    const float* p2 = pyr2 + (size_t)c * 512 * 512;
    int r0 = 64 * by - 7, c0 = 64 * bx - 7;
    for (int i = tid; i < 78 * 78; i += 256) {
        int v = i / 78, u = i - v * 78;
        int gr = r0 + v, gc = c0 + u;
        float val = 0.f;
        if (gr >= 0 && gr < 512 && gc >= 0 && gc < 512)
            val = p2[(size_t)gr * 512 + gc];
        s2[i] = val;
    }
    __syncthreads();

    dstage(s2, 78, s3, 38, 32 * by - 3, 32 * bx - 3, 256, De, Dm, tid);
    __syncthreads();
    dstage(s3, 38, s4, 18, 16 * by - 1, 16 * bx - 1, 128, De, Dm, tid);
    __syncthreads();

    float* p3 = pyr3 + (size_t)c * 256 * 256;
    for (int i = tid; i < 32 * 32; i += 256) {
        int v = i >> 5, u = i & 31;
        p3[(size_t)(32 * by + v) * 256 + 32 * bx + u] = s3[(v + 3) * 38 + u + 3];
    }
    float* p4 = pyr4 + (size_t)c * 128 * 128;
    for (int i = tid; i < 16 * 16; i += 256) {
        int v = i >> 4, u = i & 15;
        p4[(size_t)(16 * by + v) * 128 + 16 * bx + u] = s4[(v + 1) * 18 + u + 1];
    }
    float* p5 = pyr5 + (size_t)c * 64 * 64;
    for (int i = tid; i < 8 * 8; i += 256) {
        int v = i >> 3, u = i & 7;
        float acc = 0.f;
#pragma unroll
        for (int j = 0; j < 4; j++) {
            const float* row = s4 + (2 * v + j) * 18 + 2 * u;
            float wj = (j == 0 || j == 3) ? De : Dm;
            acc += wj * (De * row[0] + Dm * row[1] + Dm * row[2] + De * row[3]);
        }
        p5[(size_t)(8 * by + v) * 64 + 8 * bx + u] = acc;
    }
}

// ---------------- composite (bilinear x2 upsample -> 3-tap blur) weights ---
__device__ __forceinline__ void ub_weights(int o, int n, float w0, float w1,
                                           int& base, float w[3]) {
    base = (o >> 1) - 1;
    w[0] = w[1] = w[2] = 0.f;
    int n2 = n * 2;
#pragma unroll
    for (int d = -1; d <= 1; ++d) {
        int p = o + d;
        if (p < 0 || p >= n2) continue;
        float bw = (d == 0) ? w0 : w1;
        int i = p >> 1;
        if ((p & 1) == 0) {
            w[i - 1 - base] += 0.25f * bw;
            w[i - base]     += 0.75f * bw;
        } else {
            w[i - base]     += 0.75f * bw;
            w[i + 1 - base] += 0.25f * bw;
        }
    }
}

__device__ float up_pixel(const float* __restrict__ E, int n, int ox, int oy,
                          float w0, float w1) {
    int by, bx;
    float wy[3], wx[3];
    ub_weights(oy, n, w0, w1, by, wy);
    ub_weights(ox, n, w0, w1, bx, wx);
    int ry[3], rx[3];
#pragma unroll
    for (int j = 0; j < 3; j++) {
        ry[j] = min(max(by + j, 0), n - 1);
        rx[j] = min(max(bx + j, 0), n - 1);
    }
    float s = 0.f;
#pragma unroll
    for (int jy = 0; jy < 3; jy++) {
        const float* row = E + (size_t)ry[jy] * n;
        s += wy[jy] * (wx[0] * row[rx[0]] + wx[1] * row[rx[1]] + wx[2] * row[rx[2]]);
    }
    return s;
}

// ---------------- staged up+blur: smem-tiled, float4 stores ---------------
// Block (256 thr as 16x16) computes a 64x32 output tile of one task/channel:
// 32x16 quads from a 34x18 smem window. Interior math identical to R6;
// border quads recomputed via up_pixel before the vector store.
struct UpTasks {
    const float* in[4];
    float* out[4];
    int n[4];
};

__global__ __launch_bounds__(256)
void up_blur_smem_kernel(UpTasks T, float w0, float w1,
                         float we0, float we1, float we2) {
    __shared__ float sw[18][34];
    int task = blockIdx.z / 3;
    int c = blockIdx.z - task * 3;
    int n = T.n[task];
    int X0 = blockIdx.x * 32;          // first quad col of tile
    int Y0 = blockIdx.y * 16;          // first quad row of tile
    if (X0 >= n || Y0 >= n) return;
    const float* E = T.in[task] + (size_t)c * n * n;
    int no = 2 * n;
    float* op = T.out[task] + (size_t)c * no * no;

    int tid = threadIdx.x;
    // clamped window fill (coalesced rows of 34)
    for (int i = tid; i < 18 * 34; i += 256) {
        int r = i / 34, col = i - r * 34;
        int gr = min(max(Y0 - 1 + r, 0), n - 1);
        int gc = min(max(X0 - 1 + col, 0), n - 1);
        sw[r][col] = E[(size_t)gr * n + gc];
    }
    __syncthreads();

    int tx = tid & 15, ty = tid >> 4;
    int qy = Y0 + ty;
    int qx0 = X0 + 2 * tx;             // this thread owns quads qx0, qx0+1

    float a[3][4];
#pragma unroll
    for (int j = 0; j < 3; j++)
#pragma unroll
        for (int k = 0; k < 4; k++)
            a[j][k] = sw[ty + j][2 * tx + k];

    float r0v[4], r1v[4];              // output rows 2*qy and 2*qy+1, 4 cols
#pragma unroll
    for (int q = 0; q < 2; q++) {
        float he[3], ho[3];
#pragma unroll
        for (int j = 0; j < 3; j++) {
            float x0 = a[j][q], x1 = a[j][q + 1], x2 = a[j][q + 2];
            he[j] = we0 * x0 + we1 * x1 + we2 * x2;
            ho[j] = we2 * x0 + we1 * x1 + we0 * x2;
        }
        r0v[2 * q]     = we0 * he[0] + we1 * he[1] + we2 * he[2];
        r0v[2 * q + 1] = we0 * ho[0] + we1 * ho[1] + we2 * ho[2];
        r1v[2 * q]     = we2 * he[0] + we1 * he[1] + we0 * he[2];
        r1v[2 * q + 1] = we2 * ho[0] + we1 * ho[1] + we0 * ho[2];
    }

    // border quads: recompute exactly (clamped smem cells differ there)
    bool rowb = (qy == 0) || (qy == n - 1);
    bool b0 = rowb || (qx0 == 0);            // qx0 even, can't be n-1
    bool b1 = rowb || (qx0 + 1 == n - 1);    // qx0+1 odd, can't be 0
    if (b0 | b1) {
#pragma unroll
        for (int q = 0; q < 2; q++) {
            bool bq = q ? b1 : b0;
            if (!bq) continue;
            int qx = qx0 + q;
#pragma unroll
            for (int py = 0; py < 2; py++) {
                float v0 = up_pixel(E, n, 2 * qx,     2 * qy + py, w0, w1);
                float v1 = up_pixel(E, n, 2 * qx + 1, 2 * qy + py, w0, w1);
                if (py == 0) { r0v[2 * q] = v0; r0v[2 * q + 1] = v1; }
                else         { r1v[2 * q] = v0; r1v[2 * q + 1] = v1; }
            }
        }
    }

    float4* o0 = (float4*)(op + (size_t)(2 * qy) * no + 2 * qx0);
    float4* o1 = (float4*)(op + (size_t)(2 * qy + 1) * no + 2 * qx0);
    *o0 = make_float4(r0v[0], r0v[1], r0v[2], r0v[3]);
    *o1 = make_float4(r1v[0], r1v[1], r1v[2], r1v[3]);
}

// ---------------- blend helpers --------------------------------------------
__device__ __forceinline__ const float* level_ptr(int l, const float* E1, const float* E2,
                                                  const float* E3, const float* E4,
                                                  const float* E5) {
    const float* p = E1;
    p = (l == 2) ? E2 : p;
    p = (l == 3) ? E3 : p;
    p = (l == 4) ? E4 : p;
    p = (l == 5) ? E5 : p;
    return p;
}

__device__ __forceinline__ float blend_B(int l, float R) {
    float sprev = exp2f((float)(l - 3));
    float ap = sprev * R * (1.0f / 0.248f);
    float tp = expf(-(ap * ap) * 3.0f);
    float tc = 0.f;
    if (l < 5) {
        float ac = 2.0f * ap;
        tc = expf(-(ac * ac) * 3.0f);
    }
    return (0.5f - tc) / (tp - tc + 1e-5f);
}

__device__ void pixel_slow(int x, int y, int l, float R,
                           const float* __restrict__ img,
                           const float* __restrict__ E1, const float* __restrict__ E2,
                           const float* __restrict__ E3, const float* __restrict__ E4,
                           const float* __restrict__ E5, float* __restrict__ out,
                           float w0, float w1) {
    int pix = y * WW + x;
    if (l == 0) {
        out[pix] = img[pix];
        out[pix + HWFULL] = img[pix + HWFULL];
        out[pix + 2 * HWFULL] = img[pix + 2 * HWFULL];
        return;
    }
    float B = blend_B(l, R);
    const float* Ecur = level_ptr(l, E1, E2, E3, E4, E5);
    const float* Eprev = level_ptr(l - 1, E1, E2, E3, E4, E5);
#pragma unroll
    for (int c = 0; c < 3; c++) {
        float vc = up_pixel(Ecur + c * NE * NE, NE, x, y, w0, w1);
        float vp = (l == 1) ? img[pix + c * HWFULL]
                            : up_pixel(Eprev + c * NE * NE, NE, x, y, w0, w1);
        out[pix + c * HWFULL] = B * vp + (1.f - B) * vc;
    }
}

__device__ void quad_global(int qx, int qy, int l0, const float B[2][2],
                            const float* __restrict__ img,
                            const float* __restrict__ cur, const float* __restrict__ prv,
                            float* __restrict__ out,
                            float we0, float we1, float we2) {
    int pix0 = (2 * qy) * WW + 2 * qx;
    int wbase = (qy - 1) * NE + (qx - 1);
#pragma unroll
    for (int c = 0; c < 3; c++) {
        const float* pc = cur + c * NE * NE + wbase;
        float he[3], ho[3];
#pragma unroll
        for (int j = 0; j < 3; j++) {
            float a = pc[j * NE], b = pc[j * NE + 1], d = pc[j * NE + 2];
            he[j] = we0 * a + we1 * b + we2 * d;
            ho[j] = we2 * a + we1 * b + we0 * d;
        }
        float vc[2][2];
        vc[0][0] = we0 * he[0] + we1 * he[1] + we2 * he[2];
        vc[0][1] = we0 * ho[0] + we1 * ho[1] + we2 * ho[2];
        vc[1][0] = we2 * he[0] + we1 * he[1] + we0 * he[2];
        vc[1][1] = we2 * ho[0] + we1 * ho[1] + we0 * ho[2];

        float vp[2][2];
        if (l0 == 1) {
            float2 i0 = *(const float2*)(img + pix0 + c * HWFULL);
            float2 i1 = *(const float2*)(img + pix0 + WW + c * HWFULL);
            vp[0][0] = i0.x; vp[0][1] = i0.y; vp[1][0] = i1.x; vp[1][1] = i1.y;
        } else {
            const float* pp = prv + c * NE * NE + wbase;
            float pe[3], po[3];
#pragma unroll
            for (int j = 0; j < 3; j++) {
                float a = pp[j * NE], b = pp[j * NE + 1], d = pp[j * NE + 2];
                pe[j] = we0 * a + we1 * b + we2 * d;
                po[j] = we2 * a + we1 * b + we0 * d;
            }
            vp[0][0] = we0 * pe[0] + we1 * pe[1] + we2 * pe[2];
            vp[0][1] = we0 * po[0] + we1 * po[1] + we2 * po[2];
            vp[1][0] = we2 * pe[0] + we1 * pe[1] + we0 * pe[2];
            vp[1][1] = we2 * po[0] + we1 * po[1] + we0 * po[2];
        }
        float2 o0, o1;
        o0.x = B[0][0] * vp[0][0] + (1.f - B[0][0]) * vc[0][0];
        o0.y = B[0][1] * vp[0][1] + (1.f - B[0][1]) * vc[0][1];
        o1.x = B[1][0] * vp[1][0] + (1.f - B[1][0]) * vc[1][0];
        o1.y = B[1][1] * vp[1][1] + (1.f - B[1][1]) * vc[1][1];
        *(float2*)(out + pix0 + c * HWFULL) = o0;
        *(float2*)(out + pix0 + WW + c * HWFULL) = o1;
    }
}

// ---------------- blend: smem fast path covering 1- and 2-level blocks -----
#define TQX 32
#define TQY 8
#define TPITCH 34
#define TROWS 10

__device__ __forceinline__ float evalw(const float w[TROWS][TPITCH], int ty, int tx,
                                       int oxo, int oyo,
                                       float we0, float we1, float we2) {
    float h[3];
#pragma unroll
    for (int j = 0; j < 3; j++) {
        float a = w[ty + j][tx], b = w[ty + j][tx + 1], d = w[ty + j][tx + 2];
        h[j] = oxo ? (we2 * a + we1 * b + we0 * d) : (we0 * a + we1 * b + we2 * d);
    }
    return oyo ? (we2 * h[0] + we1 * h[1] + we0 * h[2])
               : (we0 * h[0] + we1 * h[1] + we2 * h[2]);
}

__global__ __launch_bounds__(256, 4)
void blend_quad_kernel(const float* __restrict__ img, const float* __restrict__ fixs,
                       const float* __restrict__ E1, const float* __restrict__ E2,
                       const float* __restrict__ E3, const float* __restrict__ E4,
                       const float* __restrict__ E5, float* __restrict__ out,
                       float w0, float w1, float we0, float we1, float we2,
                       float om0, float om1, float om2, float om3, float om4) {
    __shared__ float s_w[3][3][TROWS][TPITCH];
    __shared__ int s_mask;

    int tx = threadIdx.x, ty = threadIdx.y;
    int qx = blockIdx.x * TQX + tx;
    int qy = blockIdx.y * TQY + ty;
    int tid = ty * TQX + tx;

    float d2q[2][2] = {{3.4e38f, 3.4e38f}, {3.4e38f, 3.4e38f}};
    float x0 = (float)(2 * qx), y0 = (float)(2 * qy);
#pragma unroll
    for (int k = 0; k < 4; k++) {
        float dx = x0 - fixs[2 * k];
        float dy = y0 - fixs[2 * k + 1];
        float d00 = dx * dx + dy * dy;
        float tX = 2.f * dx + 1.f;
        float tY = 2.f * dy + 1.f;
        float d01 = d00 + tX;
        d2q[0][0] = fminf(d2q[0][0], d00);
        d2q[0][1] = fminf(d2q[0][1], d01);
        d2q[1][0] = fminf(d2q[1][0], d00 + tY);
        d2q[1][1] = fminf(d2q[1][1], d01 + tY);
    }

    int lv[2][2];
    float Rv[2][2];
#pragma unroll
    for (int py = 0; py < 2; py++)
#pragma unroll
        for (int px = 0; px < 2; px++) {
            float theta = sqrtf(d2q[py][px]) * (1.0f / 7.5f);
            float R = 2.5f / (theta + 2.5f);
            Rv[py][px] = R;
            lv[py][px] = (R <= om0) + (R <= om1) + (R <= om2) +
                         (R <= om3) + (R <= om4);
        }

    if (tid == 0) s_mask = 0;
    __syncthreads();
    int myMask = (1 << lv[0][0]) | (1 << lv[0][1]) | (1 << lv[1][0]) | (1 << lv[1][1]);
    atomicOr(&s_mask, myMask);
    __syncthreads();
    int mask = s_mask;
    int lmin = __ffs(mask) - 1;
    int lmax = 31 - __clz(mask);
    bool block_border = (blockIdx.x == 0) || (blockIdx.x == gridDim.x - 1) ||
                        (blockIdx.y == 0) || (blockIdx.y == gridDim.y - 1);

    int pix0 = (2 * qy) * WW + 2 * qx;

    if (!block_border && (lmax - lmin) <= 1) {
        if (mask == 1) {
#pragma unroll
            for (int c = 0; c < 3; c++) {
                *(float2*)(out + pix0 + c * HWFULL) =
                    *(const float2*)(img + pix0 + c * HWFULL);
                *(float2*)(out + pix0 + WW + c * HWFULL) =
                    *(const float2*)(img + pix0 + WW + c * HWFULL);
            }
            return;
        }
        int base = max(lmin, 1);
        bool hasP = (base >= 2);
        bool hasN = (lmax > base);
        const float* Ebase = level_ptr(base, E1, E2, E3, E4, E5);
        const float* Eprv = hasP ? level_ptr(base - 1, E1, E2, E3, E4, E5) : Ebase;
        const float* Enxt = hasN ? level_ptr(base + 1, E1, E2, E3, E4, E5) : Ebase;

        int ox0 = blockIdx.x * TQX - 1;
        int oy0 = blockIdx.y * TQY - 1;
        const int NF = 3 * TROWS * TPITCH;
        for (int i = tid; i < NF; i += 256) {
            int c = i / (TROWS * TPITCH);
            int rem = i - c * (TROWS * TPITCH);
            int r = rem / TPITCH, col = rem - r * TPITCH;
            size_t g = (size_t)c * NE * NE + (size_t)(oy0 + r) * NE + (ox0 + col);
            s_w[1][c][r][col] = Ebase[g];
            if (hasP) s_w[0][c][r][col] = Eprv[g];
            if (hasN) s_w[2][c][r][col] = Enxt[g];
        }
        __syncthreads();

        int lq = lv[0][0];
        bool uniq = (lv[0][1] == lq) && (lv[1][0] == lq) && (lv[1][1] == lq);

        if (uniq && lq == 0) {
#pragma unroll
            for (int c = 0; c < 3; c++) {
                *(float2*)(out + pix0 + c * HWFULL) =
                    *(const float2*)(img + pix0 + c * HWFULL);
                *(float2*)(out + pix0 + WW + c * HWFULL) =
                    *(const float2*)(img + pix0 + WW + c * HWFULL);
            }
            return;
        }

        if (uniq) {
            int cs = 1 + (lq - base);
            float B[2][2];
#pragma unroll
            for (int py = 0; py < 2; py++)
#pragma unroll
                for (int px = 0; px < 2; px++)
                    B[py][px] = blend_B(lq, Rv[py][px]);

#pragma unroll
            for (int c = 0; c < 3; c++) {
                const float (*wc)[TPITCH] = s_w[cs][c];
                float he[3], ho[3];
#pragma unroll
                for (int j = 0; j < 3; j++) {
                    float a = wc[ty + j][tx], b = wc[ty + j][tx + 1],
                          d = wc[ty + j][tx + 2];
                    he[j] = we0 * a + we1 * b + we2 * d;
                    ho[j] = we2 * a + we1 * b + we0 * d;
                }
                float vc[2][2];
                vc[0][0] = we0 * he[0] + we1 * he[1] + we2 * he[2];
                vc[0][1] = we0 * ho[0] + we1 * ho[1] + we2 * ho[2];
                vc[1][0] = we2 * he[0] + we1 * he[1] + we0 * he[2];
                vc[1][1] = we2 * ho[0] + we1 * ho[1] + we0 * ho[2];

                float vp[2][2];
                if (lq == 1) {
                    float2 i0 = *(const float2*)(img + pix0 + c * HWFULL);
                    float2 i1 = *(const float2*)(img + pix0 + WW + c * HWFULL);
                    vp[0][0] = i0.x; vp[0][1] = i0.y; vp[1][0] = i1.x; vp[1][1] = i1.y;
                } else {
                    const float (*wp)[TPITCH] = s_w[cs - 1][c];
                    float pe[3], po[3];
#pragma unroll
                    for (int j = 0; j < 3; j++) {
                        float a = wp[ty + j][tx], b = wp[ty + j][tx + 1],
                              d = wp[ty + j][tx + 2];
                        pe[j] = we0 * a + we1 * b + we2 * d;
                        po[j] = we2 * a + we1 * b + we0 * d;
                    }
                    vp[0][0] = we0 * pe[0] + we1 * pe[1] + we2 * pe[2];
                    vp[0][1] = we0 * po[0] + we1 * po[1] + we2 * po[2];
                    vp[1][0] = we2 * pe[0] + we1 * pe[1] + we0 * pe[2];
                    vp[1][1] = we2 * po[0] + we1 * po[1] + we0 * po[2];
                }
                float2 o0, o1;
                o0.x = B[0][0] * vp[0][0] + (1.f - B[0][0]) * vc[0][0];
                o0.y = B[0][1] * vp[0][1] + (1.f - B[0][1]) * vc[0][1];
                o1.x = B[1][0] * vp[1][0] + (1.f - B[1][0]) * vc[1][0];
                o1.y = B[1][1] * vp[1][1] + (1.f - B[1][1]) * vc[1][1];
                *(float2*)(out + pix0 + c * HWFULL) = o0;
                *(float2*)(out + pix0 + WW + c * HWFULL) = o1;
            }
            return;
        }

        float px_out[2][2][3];
#pragma unroll
        for (int py = 0; py < 2; py++)
#pragma unroll
            for (int px = 0; px < 2; px++) {
                int l = lv[py][px];
                int pp = pix0 + py * WW + px;
                if (l == 0) {
#pragma unroll
                    for (int c = 0; c < 3; c++)
                        px_out[py][px][c] = img[pp + c * HWFULL];
                } else {
                    int cs = 1 + (l - base);
                    float B = blend_B(l, Rv[py][px]);
#pragma unroll
                    for (int c = 0; c < 3; c++) {
                        float vc = evalw(s_w[cs][c], ty, tx, px, py, we0, we1, we2);
                        float vp = (l == 1) ? img[pp + c * HWFULL]
                                 : evalw(s_w[cs - 1][c], ty, tx, px, py, we0, we1, we2);
                        px_out[py][px][c] = B * vp + (1.f - B) * vc;
                    }
                }
            }
#pragma unroll
        for (int c = 0; c < 3; c++) {
            float2 o0, o1;
            o0.x = px_out[0][0][c]; o0.y = px_out[0][1][c];
            o1.x = px_out[1][0][c]; o1.y = px_out[1][1][c];
            *(float2*)(out + pix0 + c * HWFULL) = o0;
            *(float2*)(out + pix0 + WW + c * HWFULL) = o1;
        }
        return;
    }

    // fallback: border blocks / >2-level blocks (rare)
    int l0 = lv[0][0];
    bool uni = (lv[0][1] == l0) && (lv[1][0] == l0) && (lv[1][1] == l0);
    bool qborder = (qx == 0) | (qx >= NE - 1) | (qy == 0) | (qy >= NE - 1);

    if (uni && l0 == 0) {
#pragma unroll
        for (int c = 0; c < 3; c++) {
            *(float2*)(out + pix0 + c * HWFULL) =
                *(const float2*)(img + pix0 + c * HWFULL);
            *(float2*)(out + pix0 + WW + c * HWFULL) =
                *(const float2*)(img + pix0 + WW + c * HWFULL);
        }
        return;
    }
    if (!uni || qborder) {
#pragma unroll
        for (int py = 0; py < 2; py++)
#pragma unroll
            for (int px = 0; px < 2; px++)
                pixel_slow(2 * qx + px, 2 * qy + py, lv[py][px], Rv[py][px],
                           img, E1, E2, E3, E4, E5, out, w0, w1);
        return;
    }
    float B[2][2];
#pragma unroll
    for (int py = 0; py < 2; py++)
#pragma unroll
        for (int px = 0; px < 2; px++)
            B[py][px] = blend_B(l0, Rv[py][px]);
    const float* cur = level_ptr(l0, E1, E2, E3, E4, E5);
    const float* prv = level_ptr(l0 - 1, E1, E2, E3, E4, E5);
    quad_global(qx, qy, l0, B, img, cur, prv, out, we0, we1, we2);
}

// ---------------- host launch ---------------------------------------------
extern "C" void kernel_launch(void* const* d_in, const int* in_sizes, int n_in,
                              void* d_out, int out_size) {
    const float* img = (const float*)d_in[0];
    const float* fixs = (const float*)d_in[1];
    float* out = (float*)d_out;

    float *pyr1, *pyr2, *pyr3, *pyr4, *pyr5, *E2, *E3, *E4, *E5;
    float *t3a, *t4a, *t4b, *t5a, *t5b, *t5c;
    cudaGetSymbolAddress((void**)&pyr1, g_pyr1);
    cudaGetSymbolAddress((void**)&pyr2, g_pyr2);
    cudaGetSymbolAddress((void**)&pyr3, g_pyr3);
    cudaGetSymbolAddress((void**)&pyr4, g_pyr4);
    cudaGetSymbolAddress((void**)&pyr5, g_pyr5);
    cudaGetSymbolAddress((void**)&E2, g_E2);
    cudaGetSymbolAddress((void**)&E3, g_E3);
    cudaGetSymbolAddress((void**)&E4, g_E4);
    cudaGetSymbolAddress((void**)&E5, g_E5);
    cudaGetSymbolAddress((void**)&t3a, g_t3a);
    cudaGetSymbolAddress((void**)&t4a, g_t4a);
    cudaGetSymbolAddress((void**)&t4b, g_t4b);
    cudaGetSymbolAddress((void**)&t5a, g_t5a);
    cudaGetSymbolAddress((void**)&t5b, g_t5b);
    cudaGetSymbolAddress((void**)&t5c, g_t5c);

    // Gaussian taps (w2 ~ 7.5e-15 dropped from taps; kept in normalization)
    double s2 = 2.0 * 0.248 * 0.248;
    double g1 = exp(-1.0 / s2);
    double g2 = exp(-4.0 / s2);
    double nrm = 1.0 + 2.0 * g1 + 2.0 * g2;
    float w0 = (float)(1.0 / nrm);
    float w1 = (float)(g1 / nrm);
    float De = (float)(0.5 * g1 / nrm);
    float Dm = (float)(0.5 * (1.0 + g1) / nrm);
    float we0 = 0.25f * w0 + 0.75f * w1;
    float we1 = 0.75f * w0 + w1;
    float we2 = 0.25f * w1;

    double ob = sqrt(log(2.0) / 3.0) * 0.248;
    float om0 = (float)(ob * 4.0);
    float om1 = (float)(ob * 2.0);
    float om2 = (float)(ob);
    float om3 = (float)(ob * 0.5);
    float om4 = (float)(ob * 0.25);

    dim3 blk(32, 8);

    // Gaussian pyramid: two big levels + fused small chain
    blur_down_kernel<<<dim3(32, 128, 3), blk>>>(img, pyr1, 1024, De, Dm);
    blur_down_kernel<<<dim3(16, 64, 3),  blk>>>(pyr1, pyr2, 512, De, Dm);
    down_small_kernel<<<dim3(8, 8, 3), 256>>>(pyr2, pyr3, pyr4, pyr5, De, Dm);

    // Expansion chains to 1024x1024 (E maps), staged, smem-tiled
    UpTasks A; A.in[0] = pyr2; A.out[0] = E2;  A.n[0] = 512;
               A.in[1] = pyr3; A.out[1] = t3a; A.n[1] = 256;
               A.in[2] = pyr4; A.out[2] = t4a; A.n[2] = 128;
               A.in[3] = pyr5; A.out[3] = t5a; A.n[3] = 64;
    up_blur_smem_kernel<<<dim3(16, 32, 12), 256>>>(A, w0, w1, we0, we1, we2);

    UpTasks B; B.in[0] = t3a; B.out[0] = E3;  B.n[0] = 512;
               B.in[1] = t4a; B.out[1] = t4b; B.n[1] = 256;
               B.in[2] = t5a; B.out[2] = t5b; B.n[2] = 128;
               B.in[3] = 0;   B.out[3] = 0;   B.n[3] = 1;
    up_blur_smem_kernel<<<dim3(16, 32, 9), 256>>>(B, w0, w1, we0, we1, we2);

    UpTasks C; C.in[0] = t4b; C.out[0] = E4;  C.n[0] = 512;
               C.in[1] = t5b; C.out[1] = t5c; C.n[1] = 256;
               C.in[2] = 0;   C.out[2] = 0;   C.n[2] = 1;
               C.in[3] = 0;   C.out[3] = 0;   C.n[3] = 1;
    up_blur_smem_kernel<<<dim3(16, 32, 6), 256>>>(C, w0, w1, we0, we1, we2);

    UpTasks D; D.in[0] = t5c; D.out[0] = E5;  D.n[0] = 512;
               D.in[1] = 0;   D.out[1] = 0;   D.n[1] = 1;
               D.in[2] = 0;   D.out[2] = 0;   D.n[2] = 1;
               D.in[3] = 0;   D.out[3] = 0;   D.n[3] = 1;
    up_blur_smem_kernel<<<dim3(16, 32, 3), 256>>>(D, w0, w1, we0, we1, we2);

    // Final blend
    blend_quad_kernel<<<dim3(NE / 32, NE / 8), blk>>>(img, fixs, pyr1, E2, E3, E4, E5,
                                                      out, w0, w1, we0, we1, we2,
                                                      om0, om1, om2, om3, om4);
}